// round 2
// baseline (speedup 1.0000x reference)
#include <cuda_runtime.h>
#include <math.h>

#define B_   2
#define T_   2048
#define C_   1024
#define H_   16
#define HS_  64
#define TC_  3072
#define MR_  4096   // B*T

// ---------------- scratch (static device memory; no allocations) ----------------
__device__ float g_qkv[(size_t)MR_ * TC_];          // 50.3 MB
__device__ float g_q[(size_t)B_ * H_ * T_ * HS_];   // 16.8 MB (roped, head-major)
__device__ float g_k[(size_t)B_ * H_ * T_ * HS_];   // 16.8 MB
__device__ float g_v[(size_t)B_ * H_ * T_ * HS_];   // 16.8 MB
__device__ float g_y[(size_t)MR_ * C_];             // 16.8 MB (attn out, [B,T,C])

// =================================================================================
// SGEMM NT: C[M,N] = A[M,K] * B[N,K]^T   (both operands K-contiguous row-major)
// 128x128 tile, BK=8, 256 threads, 8x8 register tile, SMEM double buffered.
// M,N multiples of 128; K multiple of 8.
// =================================================================================
__global__ void __launch_bounds__(256, 2) sgemm_nt_kernel(
    const float* __restrict__ A, const float* __restrict__ Bm,
    float* __restrict__ C, int M, int N, int K)
{
    __shared__ __align__(16) float As[2][8][128];
    __shared__ __align__(16) float Bs[2][8][128];

    const int tid = threadIdx.x;
    const int bm = blockIdx.y * 128;
    const int bn = blockIdx.x * 128;

    const int lr = tid >> 1;          // 0..127
    const int lc = (tid & 1) << 2;    // 0 or 4
    const float* Ap = A + (size_t)(bm + lr) * K + lc;
    const float* Bp = Bm + (size_t)(bn + lr) * K + lc;

    const int tx = (tid & 15) << 3;   // 0..120
    const int ty = (tid >> 4) << 3;   // 0..120

    float acc[8][8];
#pragma unroll
    for (int i = 0; i < 8; i++)
#pragma unroll
        for (int j = 0; j < 8; j++) acc[i][j] = 0.f;

    // preload tile 0
    float4 a4 = *(const float4*)Ap;
    float4 b4 = *(const float4*)Bp;
    As[0][lc + 0][lr] = a4.x; As[0][lc + 1][lr] = a4.y;
    As[0][lc + 2][lr] = a4.z; As[0][lc + 3][lr] = a4.w;
    Bs[0][lc + 0][lr] = b4.x; Bs[0][lc + 1][lr] = b4.y;
    Bs[0][lc + 2][lr] = b4.z; Bs[0][lc + 3][lr] = b4.w;
    __syncthreads();

    const int nk = K >> 3;
    for (int kt = 0; kt < nk; kt++) {
        const int buf = kt & 1;
        if (kt + 1 < nk) {
            a4 = *(const float4*)(Ap + (size_t)(kt + 1) * 8);
            b4 = *(const float4*)(Bp + (size_t)(kt + 1) * 8);
        }
#pragma unroll
        for (int k = 0; k < 8; k++) {
            float ar[8], br[8];
            *(float4*)(ar)     = *(const float4*)&As[buf][k][ty];
            *(float4*)(ar + 4) = *(const float4*)&As[buf][k][ty + 4];
            *(float4*)(br)     = *(const float4*)&Bs[buf][k][tx];
            *(float4*)(br + 4) = *(const float4*)&Bs[buf][k][tx + 4];
#pragma unroll
            for (int i = 0; i < 8; i++)
#pragma unroll
                for (int j = 0; j < 8; j++) acc[i][j] += ar[i] * br[j];
        }
        if (kt + 1 < nk) {
            const int nb = buf ^ 1;
            As[nb][lc + 0][lr] = a4.x; As[nb][lc + 1][lr] = a4.y;
            As[nb][lc + 2][lr] = a4.z; As[nb][lc + 3][lr] = a4.w;
            Bs[nb][lc + 0][lr] = b4.x; Bs[nb][lc + 1][lr] = b4.y;
            Bs[nb][lc + 2][lr] = b4.z; Bs[nb][lc + 3][lr] = b4.w;
        }
        __syncthreads();
    }

#pragma unroll
    for (int i = 0; i < 8; i++) {
        float* Crow = C + (size_t)(bm + ty + i) * N + bn + tx;
        *(float4*)(Crow)     = make_float4(acc[i][0], acc[i][1], acc[i][2], acc[i][3]);
        *(float4*)(Crow + 4) = make_float4(acc[i][4], acc[i][5], acc[i][6], acc[i][7]);
    }
}

// =================================================================================
// RoPE + split into head-major Q/K/V.
// One warp per (b,h,t) row; lane i owns pair i (dims 2i, 2i+1).
// Matches the reference exactly:
//   nr[i] = r[i]*c[i] - p[i-1 mod 32]*s[i]
//   np[i] = p[i]*c[i] + nr[i+1 mod 32]*s[i]
// freq/angle/sincos in fp64 to sit at the exact value (reference's own fp32
// rounding of t*freq is then the only deviation, ~1e-4 abs worst case).
// =================================================================================
__global__ void __launch_bounds__(256) rope_split_kernel(
    const float* __restrict__ qkv,
    float* __restrict__ Q, float* __restrict__ K, float* __restrict__ V)
{
    const int w    = (blockIdx.x * blockDim.x + threadIdx.x) >> 5;  // 0..B*H*T-1
    const int lane = threadIdx.x & 31;
    const int t  = w & (T_ - 1);
    const int bh = w >> 11;            // T_=2048 -> >>11
    const int b  = bh >> 4;            // H_=16
    const int h  = bh & 15;

    const size_t row = (size_t)(b * T_ + t) * TC_;
    const int col = h * HS_ + lane * 2;

    const float2 q2 = *(const float2*)(qkv + row + col);
    const float2 k2 = *(const float2*)(qkv + row + C_ + col);
    const float2 v2 = *(const float2*)(qkv + row + 2 * C_ + col);

    const double freq = exp(-(double)lane * (9.210340371976184 / 32.0)); // 10000^(-lane/32)
    const double ang  = (double)t * freq;
    double sd, cd;
    sincos(ang, &sd, &cd);
    const float c = (float)cd, s = (float)sd;

    const unsigned FULL = 0xffffffffu;
    // Q
    float qp_prev = __shfl_sync(FULL, q2.y, (lane + 31) & 31);
    float qnr = q2.x * c - qp_prev * s;
    float qnr_next = __shfl_sync(FULL, qnr, (lane + 1) & 31);
    float qnp = q2.y * c + qnr_next * s;
    // K
    float kp_prev = __shfl_sync(FULL, k2.y, (lane + 31) & 31);
    float knr = k2.x * c - kp_prev * s;
    float knr_next = __shfl_sync(FULL, knr, (lane + 1) & 31);
    float knp = k2.y * c + knr_next * s;

    const size_t orow = ((size_t)bh * T_ + t) * HS_ + lane * 2;
    *(float2*)(Q + orow) = make_float2(qnr, qnp);
    *(float2*)(K + orow) = make_float2(knr, knp);
    *(float2*)(V + orow) = v2;
}

// =================================================================================
// Causal flash attention, fp32. BQ=64 queries, BK=32 keys per tile, 256 threads.
// Thread (tx,ty) = (tid&15, tid>>4): S frag 4 rows x 2 cols, O frag 4 rows x 4 cols.
// Q and K stored d-major (transposed) in SMEM for vectorized LDS.
// =================================================================================
__global__ void __launch_bounds__(256) attn_kernel(
    const float* __restrict__ Q, const float* __restrict__ K,
    const float* __restrict__ V, float* __restrict__ Y)
{
    __shared__ __align__(16) float Qs[64][68];   // [d][r]
    __shared__ __align__(16) float Ks[64][34];   // [d][c]
    __shared__ __align__(16) float Vs[32][68];   // [j][e]
    __shared__ __align__(16) float Ps[32][68];   // [j][r]  (S transposed, then P)
    __shared__ float sm_m[64], sm_l[64], sm_a[64];

    const int tid = threadIdx.x;
    const int tx = tid & 15;
    const int ty = tid >> 4;
    const int bh = blockIdx.y;
    const int q0 = blockIdx.x * 64;

    const float* Qp = Q + (size_t)bh * T_ * HS_;
    const float* Kp = K + (size_t)bh * T_ * HS_;
    const float* Vp = V + (size_t)bh * T_ * HS_;

    // load Q tile transposed: 64 rows x 64 dims
    {
        const int r  = tid >> 2;          // 0..63
        const int d0 = (tid & 3) * 16;    // 0,16,32,48
#pragma unroll
        for (int u = 0; u < 4; u++) {
            float4 v4 = *(const float4*)(Qp + (size_t)(q0 + r) * HS_ + d0 + u * 4);
            Qs[d0 + u * 4 + 0][r] = v4.x;
            Qs[d0 + u * 4 + 1][r] = v4.y;
            Qs[d0 + u * 4 + 2][r] = v4.z;
            Qs[d0 + u * 4 + 3][r] = v4.w;
        }
    }
    if (tid < 64) { sm_m[tid] = -1e30f; sm_l[tid] = 0.f; }

    float o[4][4];
#pragma unroll
    for (int i = 0; i < 4; i++)
#pragma unroll
        for (int e = 0; e < 4; e++) o[i][e] = 0.f;

    const int nkt = (q0 + 63) / 32 + 1;   // k-tiles with k0 <= q0+63

    for (int kt = 0; kt < nkt; kt++) {
        const int k0 = kt * 32;
        __syncthreads();   // prior consumers of Ks/Vs/Ps done

        // load K tile transposed [d][c] and V tile [j][e]
        {
            const int c  = tid >> 3;          // 0..31
            const int d0 = (tid & 7) * 8;     // 0..56
#pragma unroll
            for (int u = 0; u < 2; u++) {
                float4 v4 = *(const float4*)(Kp + (size_t)(k0 + c) * HS_ + d0 + u * 4);
                Ks[d0 + u * 4 + 0][c] = v4.x;
                Ks[d0 + u * 4 + 1][c] = v4.y;
                Ks[d0 + u * 4 + 2][c] = v4.z;
                Ks[d0 + u * 4 + 3][c] = v4.w;
            }
            *(float4*)&Vs[c][d0]     = *(const float4*)(Vp + (size_t)(k0 + c) * HS_ + d0);
            *(float4*)&Vs[c][d0 + 4] = *(const float4*)(Vp + (size_t)(k0 + c) * HS_ + d0 + 4);
        }
        __syncthreads();

        // S = Q K^T (4x2 per thread)
        float s00 = 0.f, s01 = 0.f, s10 = 0.f, s11 = 0.f;
        float s20 = 0.f, s21 = 0.f, s30 = 0.f, s31 = 0.f;
#pragma unroll
        for (int d = 0; d < 64; d++) {
            float4 qv = *(const float4*)&Qs[d][ty * 4];
            float2 kv = *(const float2*)&Ks[d][tx * 2];
            s00 += qv.x * kv.x; s01 += qv.x * kv.y;
            s10 += qv.y * kv.x; s11 += qv.y * kv.y;
            s20 += qv.z * kv.x; s21 += qv.z * kv.y;
            s30 += qv.w * kv.x; s31 += qv.w * kv.y;
        }

        // scale + causal mask, write transposed into Ps
        {
            float sv[4][2] = {{s00, s01}, {s10, s11}, {s20, s21}, {s30, s31}};
#pragma unroll
            for (int i = 0; i < 4; i++) {
                const int rg = q0 + ty * 4 + i;
#pragma unroll
                for (int j = 0; j < 2; j++) {
                    const int cg = k0 + tx * 2 + j;
                    float v = (cg > rg) ? -1e30f : sv[i][j] * 0.125f;
                    Ps[tx * 2 + j][ty * 4 + i] = v;
                }
            }
        }
        __syncthreads();

        // online softmax over the new 32 columns (one thread per query row)
        if (tid < 64) {
            const int r = tid;
            float m_old = sm_m[r];
            float mt = -1e30f;
#pragma unroll
            for (int j = 0; j < 32; j++) mt = fmaxf(mt, Ps[j][r]);
            const float m_new = fmaxf(m_old, mt);
            const float a = expf(m_old - m_new);
            float sum = 0.f;
#pragma unroll
            for (int j = 0; j < 32; j++) {
                float p = expf(Ps[j][r] - m_new);
                Ps[j][r] = p;
                sum += p;
            }
            sm_l[r] = sm_l[r] * a + sum;
            sm_m[r] = m_new;
            sm_a[r] = a;
        }
        __syncthreads();

        // rescale O, then O += P V
        {
            float a0 = sm_a[ty * 4 + 0], a1 = sm_a[ty * 4 + 1];
            float a2 = sm_a[ty * 4 + 2], a3 = sm_a[ty * 4 + 3];
#pragma unroll
            for (int e = 0; e < 4; e++) {
                o[0][e] *= a0; o[1][e] *= a1; o[2][e] *= a2; o[3][e] *= a3;
            }
        }
#pragma unroll
        for (int j = 0; j < 32; j++) {
            float4 p4 = *(const float4*)&Ps[j][ty * 4];
            float4 v4 = *(const float4*)&Vs[j][tx * 4];
            o[0][0] += p4.x * v4.x; o[0][1] += p4.x * v4.y; o[0][2] += p4.x * v4.z; o[0][3] += p4.x * v4.w;
            o[1][0] += p4.y * v4.x; o[1][1] += p4.y * v4.y; o[1][2] += p4.y * v4.z; o[1][3] += p4.y * v4.w;
            o[2][0] += p4.z * v4.x; o[2][1] += p4.z * v4.y; o[2][2] += p4.z * v4.z; o[2][3] += p4.z * v4.w;
            o[3][0] += p4.w * v4.x; o[3][1] += p4.w * v4.y; o[3][2] += p4.w * v4.z; o[3][3] += p4.w * v4.w;
        }
    }

    // finalize: divide by l, write to Y in [B,T,C] layout
    const int b = bh >> 4;
    const int h = bh & 15;
#pragma unroll
    for (int i = 0; i < 4; i++) {
        const int r = ty * 4 + i;
        const float inv_l = 1.0f / sm_l[r];
        float* yp = Y + (size_t)(b * T_ + q0 + r) * C_ + h * HS_ + tx * 4;
        *(float4*)yp = make_float4(o[i][0] * inv_l, o[i][1] * inv_l,
                                   o[i][2] * inv_l, o[i][3] * inv_l);
    }
}

// =================================================================================
// Launch
// =================================================================================
extern "C" void kernel_launch(void* const* d_in, const int* in_sizes, int n_in,
                              void* d_out, int out_size)
{
    (void)in_sizes; (void)n_in; (void)out_size;
    const float* x      = (const float*)d_in[0];
    const float* w_attn = (const float*)d_in[1];
    const float* w_proj = (const float*)d_in[2];
    float* out = (float*)d_out;

    float *qkv, *q, *k, *v, *y;
    cudaGetSymbolAddress((void**)&qkv, g_qkv);
    cudaGetSymbolAddress((void**)&q,   g_q);
    cudaGetSymbolAddress((void**)&k,   g_k);
    cudaGetSymbolAddress((void**)&v,   g_v);
    cudaGetSymbolAddress((void**)&y,   g_y);

    // 1) QKV = x @ w_attn^T : [4096,1024] x [3072,1024]^T
    {
        dim3 grid(TC_ / 128, MR_ / 128);   // (24, 32)
        sgemm_nt_kernel<<<grid, 256>>>(x, w_attn, qkv, MR_, TC_, C_);
    }
    // 2) RoPE + head split
    {
        const int warps = B_ * H_ * T_;          // 65536
        rope_split_kernel<<<warps * 32 / 256, 256>>>(qkv, q, k, v);
    }
    // 3) causal flash attention
    {
        dim3 grid(T_ / 64, B_ * H_);             // (32, 32)
        attn_kernel<<<grid, 256>>>(q, k, v, y);
    }
    // 4) out = y @ w_proj^T : [4096,1024] x [1024,1024]^T
    {
        dim3 grid(C_ / 128, MR_ / 128);          // (8, 32)
        sgemm_nt_kernel<<<grid, 256>>>(y, w_proj, out, MR_, C_, C_);
    }
}

// round 4
// speedup vs baseline: 1.2765x; 1.2765x over previous
#include <cuda_runtime.h>
#include <cuda_bf16.h>
#include <math.h>
#include <stdint.h>

#define B_   2
#define T_   2048
#define C_   1024
#define H_   16
#define HS_  64
#define TC_  3072
#define MR_  4096   // B*T
#define KP_  3072   // split K' = 3*1024

// ---------------- scratch (static device memory; no allocations) ----------------
__device__ float g_qkv[(size_t)MR_ * TC_];
__device__ float g_q[(size_t)B_ * H_ * T_ * HS_];
__device__ float g_k[(size_t)B_ * H_ * T_ * HS_];
__device__ float g_v[(size_t)B_ * H_ * T_ * HS_];
__device__ float g_y[(size_t)MR_ * C_];
__device__ uint16_t g_xs[(size_t)MR_ * KP_];
__device__ uint16_t g_was[(size_t)TC_ * KP_];
__device__ uint16_t g_wps[(size_t)C_ * KP_];
__device__ uint16_t g_ys[(size_t)MR_ * KP_];

// ======================= helpers =======================
__device__ __forceinline__ uint32_t smem_u32(const void* p) {
    uint32_t a;
    asm("{ .reg .u64 t; cvta.to.shared.u64 t, %1; cvt.u32.u64 %0, t; }" : "=r"(a) : "l"(p));
    return a;
}
__device__ __forceinline__ void cp_async16(uint32_t dst, const void* src) {
    asm volatile("cp.async.cg.shared.global [%0], [%1], 16;" :: "r"(dst), "l"(src));
}
#define CP_COMMIT() asm volatile("cp.async.commit_group;" ::: "memory")
#define CP_WAIT(n)  asm volatile("cp.async.wait_group %0;" :: "n"(n) : "memory")

__device__ __forceinline__ void ldsm_x4(uint32_t& r0, uint32_t& r1, uint32_t& r2, uint32_t& r3,
                                        uint32_t addr) {
    asm volatile("ldmatrix.sync.aligned.m8n8.x4.shared.b16 {%0,%1,%2,%3}, [%4];"
                 : "=r"(r0), "=r"(r1), "=r"(r2), "=r"(r3) : "r"(addr));
}
__device__ __forceinline__ void mma16816(float* c, uint32_t a0, uint32_t a1, uint32_t a2,
                                         uint32_t a3, uint32_t b0, uint32_t b1) {
    asm volatile(
        "mma.sync.aligned.m16n8k16.row.col.f32.bf16.bf16.f32 "
        "{%0,%1,%2,%3}, {%4,%5,%6,%7}, {%8,%9}, {%0,%1,%2,%3};"
        : "+f"(c[0]), "+f"(c[1]), "+f"(c[2]), "+f"(c[3])
        : "r"(a0), "r"(a1), "r"(a2), "r"(a3), "r"(b0), "r"(b1));
}

// ======================= split-bf16 conversion =======================
// in: fp32 [R,1024]. out: bf16(u16) [R,3072]: modeA=1 -> (hi,lo,hi), else (hi,hi,lo)
__global__ void __launch_bounds__(256) split_bf16_kernel(
    const float* __restrict__ in, uint16_t* __restrict__ out, int modeA, int total)
{
    int idx = blockIdx.x * 256 + threadIdx.x;
    if (idx >= total) return;
    const int r = idx >> 10;
    const int c = idx & 1023;
    const float v = in[idx];
    const __nv_bfloat16 hb = __float2bfloat16(v);
    const float hf = __bfloat162float(hb);
    const __nv_bfloat16 lb = __float2bfloat16(v - hf);
    const uint16_t hu = __nv_bfloat16_raw(hb).x;
    const uint16_t lu = __nv_bfloat16_raw(lb).x;
    const size_t base = (size_t)r * KP_ + c;
    if (modeA) { out[base] = hu; out[base + 1024] = lu; out[base + 2048] = hu; }
    else       { out[base] = hu; out[base + 1024] = hu; out[base + 2048] = lu; }
}

// ======================= mma.sync bf16 GEMM =======================
// C[M,N] fp32 = A'[M,3072] * B'[N,3072]^T.  Block 128x128xBK32, 8 warps (2x4),
// warp tile 64x32, mma m16n8k16, cp.async double buffer.
#define BK_   32
#define NKT_  (KP_ / BK_)   // 96
#define LDA_  40            // smem row stride (elems) -> 80B, conflict-free ldmatrix

__global__ void __launch_bounds__(256) gemm_mma_kernel(
    const uint16_t* __restrict__ A, const uint16_t* __restrict__ Bm,
    float* __restrict__ C, int N)
{
    __shared__ __align__(16) uint16_t As[2][128 * LDA_];
    __shared__ __align__(16) uint16_t Bs[2][128 * LDA_];

    const int tid  = threadIdx.x;
    const int wid  = tid >> 5;
    const int lane = tid & 31;
    const int wm = wid & 1;        // 0..1  (m)
    const int wn = wid >> 1;       // 0..3  (n)
    const int bm = blockIdx.y * 128;
    const int bn = blockIdx.x * 128;

    const uint32_t sA[2] = { smem_u32(As[0]), smem_u32(As[1]) };
    const uint32_t sB[2] = { smem_u32(Bs[0]), smem_u32(Bs[1]) };

    // loader coords: 2 threads per row, each 32B (2x16B)
    const int lrow = tid >> 1;
    const int lhalf = tid & 1;
    const uint16_t* Ag = A + (size_t)(bm + lrow) * KP_ + lhalf * 16;
    const uint16_t* Bg = Bm + (size_t)(bn + lrow) * KP_ + lhalf * 16;
    const uint32_t ldst = lrow * (LDA_ * 2) + lhalf * 32;   // byte offset in tile

    // ldmatrix per-lane byte offsets (within a buffer)
    // A frag (m-tile mi, kstep ks): row = wm*64+mi*16 + ((lane>>3)&1)*8 + (lane&7), kcol = ks*16 + ((lane>>4)&1)*8
    const int a_row_l = ((lane >> 3) & 1) * 8 + (lane & 7);
    const int a_koff  = ((lane >> 4) & 1) * 8;
    // B frag (n-pair np, ks): row = wn*32+np*16 + ((lane>>4)&1)*8 + (lane&7), kcol = ks*16 + ((lane>>3)&1)*8
    const int b_row_l = ((lane >> 4) & 1) * 8 + (lane & 7);
    const int b_koff  = ((lane >> 3) & 1) * 8;

    float acc[4][4][4];
#pragma unroll
    for (int mi = 0; mi < 4; mi++)
#pragma unroll
        for (int ni = 0; ni < 4; ni++)
#pragma unroll
            for (int e = 0; e < 4; e++) acc[mi][ni][e] = 0.f;

    auto load_tile = [&](int kt, int buf) {
        const uint16_t* ag = Ag + (size_t)kt * BK_;
        const uint16_t* bg = Bg + (size_t)kt * BK_;
        cp_async16(sA[buf] + ldst,      ag);
        cp_async16(sA[buf] + ldst + 16, ag + 8);
        cp_async16(sB[buf] + ldst,      bg);
        cp_async16(sB[buf] + ldst + 16, bg + 8);
    };

    load_tile(0, 0);
    CP_COMMIT();

    for (int kt = 0; kt < NKT_; kt++) {
        const int buf = kt & 1;
        if (kt + 1 < NKT_) { load_tile(kt + 1, buf ^ 1); CP_COMMIT(); CP_WAIT(1); }
        else               { CP_WAIT(0); }
        __syncthreads();

#pragma unroll
        for (int ks = 0; ks < 2; ks++) {
            uint32_t a[4][4];
#pragma unroll
            for (int mi = 0; mi < 4; mi++) {
                const int row = wm * 64 + mi * 16 + a_row_l;
                const uint32_t addr = sA[buf] + (row * LDA_ + ks * 16 + a_koff) * 2;
                ldsm_x4(a[mi][0], a[mi][1], a[mi][2], a[mi][3], addr);
            }
            uint32_t b[4][2];
#pragma unroll
            for (int np = 0; np < 2; np++) {
                const int row = wn * 32 + np * 16 + b_row_l;
                const uint32_t addr = sB[buf] + (row * LDA_ + ks * 16 + b_koff) * 2;
                ldsm_x4(b[np * 2][0], b[np * 2][1], b[np * 2 + 1][0], b[np * 2 + 1][1], addr);
            }
#pragma unroll
            for (int mi = 0; mi < 4; mi++)
#pragma unroll
                for (int ni = 0; ni < 4; ni++)
                    mma16816(acc[mi][ni], a[mi][0], a[mi][1], a[mi][2], a[mi][3],
                             b[ni][0], b[ni][1]);
        }
        __syncthreads();
    }

    // epilogue: c0,c1 -> row = lane>>2, cols (lane&3)*2..+1 ; c2,c3 -> row+8
    const int er = lane >> 2;
    const int ec = (lane & 3) * 2;
#pragma unroll
    for (int mi = 0; mi < 4; mi++) {
#pragma unroll
        for (int ni = 0; ni < 4; ni++) {
            const int r0 = bm + wm * 64 + mi * 16 + er;
            const int c0 = bn + wn * 32 + ni * 8 + ec;
            *(float2*)(C + (size_t)r0 * N + c0)       = make_float2(acc[mi][ni][0], acc[mi][ni][1]);
            *(float2*)(C + (size_t)(r0 + 8) * N + c0) = make_float2(acc[mi][ni][2], acc[mi][ni][3]);
        }
    }
}

// ======================= RoPE + head split =======================
__global__ void __launch_bounds__(256) rope_split_kernel(
    const float* __restrict__ qkv,
    float* __restrict__ Q, float* __restrict__ K, float* __restrict__ V)
{
    const int w    = (blockIdx.x * blockDim.x + threadIdx.x) >> 5;
    const int lane = threadIdx.x & 31;
    const int t  = w & (T_ - 1);
    const int bh = w >> 11;
    const int b  = bh >> 4;
    const int h  = bh & 15;

    const size_t row = (size_t)(b * T_ + t) * TC_;
    const int col = h * HS_ + lane * 2;

    const float2 q2 = *(const float2*)(qkv + row + col);
    const float2 k2 = *(const float2*)(qkv + row + C_ + col);
    const float2 v2 = *(const float2*)(qkv + row + 2 * C_ + col);

    const double freq = exp(-(double)lane * (9.210340371976184 / 32.0));
    const double ang  = (double)t * freq;
    double sd, cd;
    sincos(ang, &sd, &cd);
    const float c = (float)cd, s = (float)sd;

    const unsigned FULL = 0xffffffffu;
    float qp_prev = __shfl_sync(FULL, q2.y, (lane + 31) & 31);
    float qnr = q2.x * c - qp_prev * s;
    float qnr_next = __shfl_sync(FULL, qnr, (lane + 1) & 31);
    float qnp = q2.y * c + qnr_next * s;
    float kp_prev = __shfl_sync(FULL, k2.y, (lane + 31) & 31);
    float knr = k2.x * c - kp_prev * s;
    float knr_next = __shfl_sync(FULL, knr, (lane + 1) & 31);
    float knp = k2.y * c + knr_next * s;

    const size_t orow = ((size_t)bh * T_ + t) * HS_ + lane * 2;
    *(float2*)(Q + orow) = make_float2(qnr, qnp);
    *(float2*)(K + orow) = make_float2(knr, knp);
    *(float2*)(V + orow) = v2;
}

// ======================= causal flash attention (fp32, __expf) =======================
__global__ void __launch_bounds__(256) attn_kernel(
    const float* __restrict__ Q, const float* __restrict__ K,
    const float* __restrict__ V, float* __restrict__ Y)
{
    __shared__ __align__(16) float Qs[64][68];
    __shared__ __align__(16) float Ks[64][34];
    __shared__ __align__(16) float Vs[32][68];
    __shared__ __align__(16) float Ps[32][68];
    __shared__ float sm_m[64], sm_l[64], sm_a[64];

    const int tid = threadIdx.x;
    const int tx = tid & 15;
    const int ty = tid >> 4;
    const int bh = blockIdx.y;
    const int q0 = blockIdx.x * 64;

    const float* Qp = Q + (size_t)bh * T_ * HS_;
    const float* Kp = K + (size_t)bh * T_ * HS_;
    const float* Vp = V + (size_t)bh * T_ * HS_;

    {
        const int r  = tid >> 2;
        const int d0 = (tid & 3) * 16;
#pragma unroll
        for (int u = 0; u < 4; u++) {
            float4 v4 = *(const float4*)(Qp + (size_t)(q0 + r) * HS_ + d0 + u * 4);
            Qs[d0 + u * 4 + 0][r] = v4.x;
            Qs[d0 + u * 4 + 1][r] = v4.y;
            Qs[d0 + u * 4 + 2][r] = v4.z;
            Qs[d0 + u * 4 + 3][r] = v4.w;
        }
    }
    if (tid < 64) { sm_m[tid] = -1e30f; sm_l[tid] = 0.f; }

    float o[4][4];
#pragma unroll
    for (int i = 0; i < 4; i++)
#pragma unroll
        for (int e = 0; e < 4; e++) o[i][e] = 0.f;

    const int nkt = (q0 + 63) / 32 + 1;

    for (int kt = 0; kt < nkt; kt++) {
        const int k0 = kt * 32;
        __syncthreads();
        {
            const int c  = tid >> 3;
            const int d0 = (tid & 7) * 8;
#pragma unroll
            for (int u = 0; u < 2; u++) {
                float4 v4 = *(const float4*)(Kp + (size_t)(k0 + c) * HS_ + d0 + u * 4);
                Ks[d0 + u * 4 + 0][c] = v4.x;
                Ks[d0 + u * 4 + 1][c] = v4.y;
                Ks[d0 + u * 4 + 2][c] = v4.z;
                Ks[d0 + u * 4 + 3][c] = v4.w;
            }
            *(float4*)&Vs[c][d0]     = *(const float4*)(Vp + (size_t)(k0 + c) * HS_ + d0);
            *(float4*)&Vs[c][d0 + 4] = *(const float4*)(Vp + (size_t)(k0 + c) * HS_ + d0 + 4);
        }
        __syncthreads();

        float s00 = 0.f, s01 = 0.f, s10 = 0.f, s11 = 0.f;
        float s20 = 0.f, s21 = 0.f, s30 = 0.f, s31 = 0.f;
#pragma unroll
        for (int d = 0; d < 64; d++) {
            float4 qv = *(const float4*)&Qs[d][ty * 4];
            float2 kv = *(const float2*)&Ks[d][tx * 2];
            s00 += qv.x * kv.x; s01 += qv.x * kv.y;
            s10 += qv.y * kv.x; s11 += qv.y * kv.y;
            s20 += qv.z * kv.x; s21 += qv.z * kv.y;
            s30 += qv.w * kv.x; s31 += qv.w * kv.y;
        }

        {
            float sv[4][2] = {{s00, s01}, {s10, s11}, {s20, s21}, {s30, s31}};
#pragma unroll
            for (int i = 0; i < 4; i++) {
                const int rg = q0 + ty * 4 + i;
#pragma unroll
                for (int j = 0; j < 2; j++) {
                    const int cg = k0 + tx * 2 + j;
                    float v = (cg > rg) ? -1e30f : sv[i][j] * 0.125f;
                    Ps[tx * 2 + j][ty * 4 + i] = v;
                }
            }
        }
        __syncthreads();

        if (tid < 64) {
            const int rr = tid;
            float m_old = sm_m[rr];
            float mt = -1e30f;
#pragma unroll
            for (int j = 0; j < 32; j++) mt = fmaxf(mt, Ps[j][rr]);
            const float m_new = fmaxf(m_old, mt);
            const float a = __expf(m_old - m_new);
            float sum = 0.f;
#pragma unroll
            for (int j = 0; j < 32; j++) {
                float p = __expf(Ps[j][rr] - m_new);
                Ps[j][rr] = p;
                sum += p;
            }
            sm_l[rr] = sm_l[rr] * a + sum;
            sm_m[rr] = m_new;
            sm_a[rr] = a;
        }
        __syncthreads();

        {
            float a0 = sm_a[ty * 4 + 0], a1 = sm_a[ty * 4 + 1];
            float a2 = sm_a[ty * 4 + 2], a3 = sm_a[ty * 4 + 3];
#pragma unroll
            for (int e = 0; e < 4; e++) {
                o[0][e] *= a0; o[1][e] *= a1; o[2][e] *= a2; o[3][e] *= a3;
            }
        }
#pragma unroll
        for (int j = 0; j < 32; j++) {
            float4 p4 = *(const float4*)&Ps[j][ty * 4];
            float4 v4 = *(const float4*)&Vs[j][tx * 4];
            o[0][0] += p4.x * v4.x; o[0][1] += p4.x * v4.y; o[0][2] += p4.x * v4.z; o[0][3] += p4.x * v4.w;
            o[1][0] += p4.y * v4.x; o[1][1] += p4.y * v4.y; o[1][2] += p4.y * v4.z; o[1][3] += p4.y * v4.w;
            o[2][0] += p4.z * v4.x; o[2][1] += p4.z * v4.y; o[2][2] += p4.z * v4.z; o[2][3] += p4.z * v4.w;
            o[3][0] += p4.w * v4.x; o[3][1] += p4.w * v4.y; o[3][2] += p4.w * v4.z; o[3][3] += p4.w * v4.w;
        }
    }

    const int b = bh >> 4;
    const int h = bh & 15;
#pragma unroll
    for (int i = 0; i < 4; i++) {
        const int rr = ty * 4 + i;
        const float inv_l = 1.0f / sm_l[rr];
        float* yp = Y + (size_t)(b * T_ + q0 + rr) * C_ + h * HS_ + tx * 4;
        *(float4*)yp = make_float4(o[i][0] * inv_l, o[i][1] * inv_l,
                                   o[i][2] * inv_l, o[i][3] * inv_l);
    }
}

// ======================= launch =======================
extern "C" void kernel_launch(void* const* d_in, const int* in_sizes, int n_in,
                              void* d_out, int out_size)
{
    (void)in_sizes; (void)n_in; (void)out_size;
    const float* x      = (const float*)d_in[0];
    const float* w_attn = (const float*)d_in[1];
    const float* w_proj = (const float*)d_in[2];
    float* out = (float*)d_out;

    float *qkv, *q, *k, *v, *y;
    uint16_t *xs, *was, *wps, *ys;
    cudaGetSymbolAddress((void**)&qkv, g_qkv);
    cudaGetSymbolAddress((void**)&q,   g_q);
    cudaGetSymbolAddress((void**)&k,   g_k);
    cudaGetSymbolAddress((void**)&v,   g_v);
    cudaGetSymbolAddress((void**)&y,   g_y);
    cudaGetSymbolAddress((void**)&xs,  g_xs);
    cudaGetSymbolAddress((void**)&was, g_was);
    cudaGetSymbolAddress((void**)&wps, g_wps);
    cudaGetSymbolAddress((void**)&ys,  g_ys);

    // 0) split conversions of x, w_attn, w_proj
    {
        int n1 = MR_ * C_;
        split_bf16_kernel<<<(n1 + 255) / 256, 256>>>(x, xs, 1, n1);
        int n2 = TC_ * C_;
        split_bf16_kernel<<<(n2 + 255) / 256, 256>>>(w_attn, was, 0, n2);
        int n3 = C_ * C_;
        split_bf16_kernel<<<(n3 + 255) / 256, 256>>>(w_proj, wps, 0, n3);
    }
    // 1) QKV = x' @ w_attn'^T  (tensor cores via mma.sync)
    {
        dim3 grid(TC_ / 128, MR_ / 128);   // (24, 32)
        gemm_mma_kernel<<<grid, 256>>>(xs, was, qkv, TC_);
    }
    // 2) RoPE + head split
    {
        const int warps = B_ * H_ * T_;
        rope_split_kernel<<<warps * 32 / 256, 256>>>(qkv, q, k, v);
    }
    // 3) causal flash attention
    {
        dim3 grid(T_ / 64, B_ * H_);
        attn_kernel<<<grid, 256>>>(q, k, v, y);
    }
    // 4) split y, then out = y' @ w_proj'^T
    {
        int n4 = MR_ * C_;
        split_bf16_kernel<<<(n4 + 255) / 256, 256>>>(y, ys, 1, n4);
        dim3 grid(C_ / 128, MR_ / 128);    // (8, 32)
        gemm_mma_kernel<<<grid, 256>>>(ys, wps, out, C_);
    }
}

// round 7
// speedup vs baseline: 2.0151x; 1.5787x over previous
#include <cuda_runtime.h>
#include <cuda_bf16.h>
#include <math.h>
#include <stdint.h>

#define B_   2
#define T_   2048
#define C_   1024
#define H_   16
#define HS_  64
#define TC_  3072
#define MR_  4096   // B*T
#define KP_  3072   // split K' = 3*1024

// ---------------- scratch (static device memory; no allocations) ----------------
__device__ float g_qkv[(size_t)MR_ * TC_];
__device__ uint16_t g_xs[(size_t)MR_ * KP_];
__device__ uint16_t g_was[(size_t)TC_ * KP_];
__device__ uint16_t g_wps[(size_t)C_ * KP_];
__device__ uint16_t g_ys[(size_t)MR_ * KP_];
// split Q/K/V (hi/lo bf16), head-major [B*H, T, 64]
__device__ uint16_t g_qh[(size_t)B_ * H_ * T_ * HS_];
__device__ uint16_t g_ql[(size_t)B_ * H_ * T_ * HS_];
__device__ uint16_t g_kh[(size_t)B_ * H_ * T_ * HS_];
__device__ uint16_t g_kl[(size_t)B_ * H_ * T_ * HS_];
__device__ uint16_t g_vh[(size_t)B_ * H_ * T_ * HS_];
__device__ uint16_t g_vl[(size_t)B_ * H_ * T_ * HS_];

// ======================= helpers =======================
__device__ __forceinline__ uint32_t smem_u32(const void* p) {
    uint32_t a;
    asm("{ .reg .u64 t; cvta.to.shared.u64 t, %1; cvt.u32.u64 %0, t; }" : "=r"(a) : "l"(p));
    return a;
}
__device__ __forceinline__ void cp_async16(uint32_t dst, const void* src) {
    asm volatile("cp.async.cg.shared.global [%0], [%1], 16;" :: "r"(dst), "l"(src));
}
#define CP_COMMIT() asm volatile("cp.async.commit_group;" ::: "memory")
#define CP_WAIT(n)  asm volatile("cp.async.wait_group %0;" :: "n"(n) : "memory")

__device__ __forceinline__ void ldsm_x4(uint32_t& r0, uint32_t& r1, uint32_t& r2, uint32_t& r3,
                                        uint32_t addr) {
    asm volatile("ldmatrix.sync.aligned.m8n8.x4.shared.b16 {%0,%1,%2,%3}, [%4];"
                 : "=r"(r0), "=r"(r1), "=r"(r2), "=r"(r3) : "r"(addr));
}
__device__ __forceinline__ void ldsm_x4_t(uint32_t& r0, uint32_t& r1, uint32_t& r2, uint32_t& r3,
                                          uint32_t addr) {
    asm volatile("ldmatrix.sync.aligned.m8n8.x4.trans.shared.b16 {%0,%1,%2,%3}, [%4];"
                 : "=r"(r0), "=r"(r1), "=r"(r2), "=r"(r3) : "r"(addr));
}
__device__ __forceinline__ void mma16816(float* c, uint32_t a0, uint32_t a1, uint32_t a2,
                                         uint32_t a3, uint32_t b0, uint32_t b1) {
    asm volatile(
        "mma.sync.aligned.m16n8k16.row.col.f32.bf16.bf16.f32 "
        "{%0,%1,%2,%3}, {%4,%5,%6,%7}, {%8,%9}, {%0,%1,%2,%3};"
        : "+f"(c[0]), "+f"(c[1]), "+f"(c[2]), "+f"(c[3])
        : "r"(a0), "r"(a1), "r"(a2), "r"(a3), "r"(b0), "r"(b1));
}
// split two floats into packed (hi,hi) and (lo,lo) bf16x2
__device__ __forceinline__ void split2(float a, float b, uint32_t& hi, uint32_t& lo) {
    __nv_bfloat16 ha = __float2bfloat16(a), hb = __float2bfloat16(b);
    float fa = __bfloat162float(ha), fb = __bfloat162float(hb);
    __nv_bfloat16 la = __float2bfloat16(a - fa), lb = __float2bfloat16(b - fb);
    hi = (uint32_t)__nv_bfloat16_raw(ha).x | ((uint32_t)__nv_bfloat16_raw(hb).x << 16);
    lo = (uint32_t)__nv_bfloat16_raw(la).x | ((uint32_t)__nv_bfloat16_raw(lb).x << 16);
}

// ======================= split-bf16 conversion (inputs) =======================
__global__ void __launch_bounds__(256) split_bf16_kernel(
    const float* __restrict__ in, uint16_t* __restrict__ out, int modeA, int total)
{
    int idx = blockIdx.x * 256 + threadIdx.x;
    if (idx >= total) return;
    const int r = idx >> 10;
    const int c = idx & 1023;
    const float v = in[idx];
    const __nv_bfloat16 hb = __float2bfloat16(v);
    const float hf = __bfloat162float(hb);
    const __nv_bfloat16 lb = __float2bfloat16(v - hf);
    const uint16_t hu = __nv_bfloat16_raw(hb).x;
    const uint16_t lu = __nv_bfloat16_raw(lb).x;
    const size_t base = (size_t)r * KP_ + c;
    if (modeA) { out[base] = hu; out[base + 1024] = lu; out[base + 2048] = hu; }
    else       { out[base] = hu; out[base + 1024] = hu; out[base + 2048] = lu; }
}

// ======================= mma.sync bf16 GEMM (proven R4) =======================
#define BK_   32
#define NKT_  (KP_ / BK_)   // 96
#define LDA_  40

__global__ void __launch_bounds__(256) gemm_mma_kernel(
    const uint16_t* __restrict__ A, const uint16_t* __restrict__ Bm,
    float* __restrict__ C, int N)
{
    __shared__ __align__(16) uint16_t As[2][128 * LDA_];
    __shared__ __align__(16) uint16_t Bs[2][128 * LDA_];

    const int tid  = threadIdx.x;
    const int wid  = tid >> 5;
    const int lane = tid & 31;
    const int wm = wid & 1;
    const int wn = wid >> 1;
    const int bm = blockIdx.y * 128;
    const int bn = blockIdx.x * 128;

    const uint32_t sA[2] = { smem_u32(As[0]), smem_u32(As[1]) };
    const uint32_t sB[2] = { smem_u32(Bs[0]), smem_u32(Bs[1]) };

    const int lrow = tid >> 1;
    const int lhalf = tid & 1;
    const uint16_t* Ag = A + (size_t)(bm + lrow) * KP_ + lhalf * 16;
    const uint16_t* Bg = Bm + (size_t)(bn + lrow) * KP_ + lhalf * 16;
    const uint32_t ldst = lrow * (LDA_ * 2) + lhalf * 32;

    const int a_row_l = ((lane >> 3) & 1) * 8 + (lane & 7);
    const int a_koff  = ((lane >> 4) & 1) * 8;
    const int b_row_l = ((lane >> 4) & 1) * 8 + (lane & 7);
    const int b_koff  = ((lane >> 3) & 1) * 8;

    float acc[4][4][4];
#pragma unroll
    for (int mi = 0; mi < 4; mi++)
#pragma unroll
        for (int ni = 0; ni < 4; ni++)
#pragma unroll
            for (int e = 0; e < 4; e++) acc[mi][ni][e] = 0.f;

    auto load_tile = [&](int kt, int buf) {
        const uint16_t* ag = Ag + (size_t)kt * BK_;
        const uint16_t* bg = Bg + (size_t)kt * BK_;
        cp_async16(sA[buf] + ldst,      ag);
        cp_async16(sA[buf] + ldst + 16, ag + 8);
        cp_async16(sB[buf] + ldst,      bg);
        cp_async16(sB[buf] + ldst + 16, bg + 8);
    };

    load_tile(0, 0);
    CP_COMMIT();

    for (int kt = 0; kt < NKT_; kt++) {
        const int buf = kt & 1;
        if (kt + 1 < NKT_) { load_tile(kt + 1, buf ^ 1); CP_COMMIT(); CP_WAIT(1); }
        else               { CP_WAIT(0); }
        __syncthreads();

#pragma unroll
        for (int ks = 0; ks < 2; ks++) {
            uint32_t a[4][4];
#pragma unroll
            for (int mi = 0; mi < 4; mi++) {
                const int row = wm * 64 + mi * 16 + a_row_l;
                ldsm_x4(a[mi][0], a[mi][1], a[mi][2], a[mi][3],
                        sA[buf] + (row * LDA_ + ks * 16 + a_koff) * 2);
            }
            uint32_t b[4][2];
#pragma unroll
            for (int np = 0; np < 2; np++) {
                const int row = wn * 32 + np * 16 + b_row_l;
                ldsm_x4(b[np * 2][0], b[np * 2][1], b[np * 2 + 1][0], b[np * 2 + 1][1],
                        sB[buf] + (row * LDA_ + ks * 16 + b_koff) * 2);
            }
#pragma unroll
            for (int mi = 0; mi < 4; mi++)
#pragma unroll
                for (int ni = 0; ni < 4; ni++)
                    mma16816(acc[mi][ni], a[mi][0], a[mi][1], a[mi][2], a[mi][3],
                             b[ni][0], b[ni][1]);
        }
        __syncthreads();
    }

    const int er = lane >> 2;
    const int ec = (lane & 3) * 2;
#pragma unroll
    for (int mi = 0; mi < 4; mi++) {
#pragma unroll
        for (int ni = 0; ni < 4; ni++) {
            const int r0 = bm + wm * 64 + mi * 16 + er;
            const int c0 = bn + wn * 32 + ni * 8 + ec;
            *(float2*)(C + (size_t)r0 * N + c0)       = make_float2(acc[mi][ni][0], acc[mi][ni][1]);
            *(float2*)(C + (size_t)(r0 + 8) * N + c0) = make_float2(acc[mi][ni][2], acc[mi][ni][3]);
        }
    }
}

// ======================= RoPE + head split -> split-bf16 Q/K/V =======================
__global__ void __launch_bounds__(256) rope_split_kernel(
    const float* __restrict__ qkv,
    uint16_t* __restrict__ qh, uint16_t* __restrict__ ql,
    uint16_t* __restrict__ kh, uint16_t* __restrict__ kl,
    uint16_t* __restrict__ vh, uint16_t* __restrict__ vl)
{
    const int w    = (blockIdx.x * blockDim.x + threadIdx.x) >> 5;
    const int lane = threadIdx.x & 31;
    const int t  = w & (T_ - 1);
    const int bh = w >> 11;
    const int b  = bh >> 4;
    const int h  = bh & 15;

    const size_t row = (size_t)(b * T_ + t) * TC_;
    const int col = h * HS_ + lane * 2;

    const float2 q2 = *(const float2*)(qkv + row + col);
    const float2 k2 = *(const float2*)(qkv + row + C_ + col);
    const float2 v2 = *(const float2*)(qkv + row + 2 * C_ + col);

    const double freq = exp(-(double)lane * (9.210340371976184 / 32.0));
    const double ang  = (double)t * freq;
    double sd, cd;
    sincos(ang, &sd, &cd);
    const float c = (float)cd, s = (float)sd;

    const unsigned FULL = 0xffffffffu;
    float qp_prev = __shfl_sync(FULL, q2.y, (lane + 31) & 31);
    float qnr = q2.x * c - qp_prev * s;
    float qnr_next = __shfl_sync(FULL, qnr, (lane + 1) & 31);
    float qnp = q2.y * c + qnr_next * s;
    float kp_prev = __shfl_sync(FULL, k2.y, (lane + 31) & 31);
    float knr = k2.x * c - kp_prev * s;
    float knr_next = __shfl_sync(FULL, knr, (lane + 1) & 31);
    float knp = k2.y * c + knr_next * s;

    const size_t o = ((size_t)bh * T_ + t) * HS_ + lane * 2;
    uint32_t hi, lo;
    split2(qnr, qnp, hi, lo);
    *(uint32_t*)(qh + o) = hi; *(uint32_t*)(ql + o) = lo;
    split2(knr, knp, hi, lo);
    *(uint32_t*)(kh + o) = hi; *(uint32_t*)(kl + o) = lo;
    split2(v2.x, v2.y, hi, lo);
    *(uint32_t*)(vh + o) = hi; *(uint32_t*)(vl + o) = lo;
}

// ======================= tensor-core causal flash attention =======================
// 128 q per block, 64 kv per tile, 8 warps (16 q rows each, full kv range).
#define AT_ROWB 144                 // 72 elems * 2B per smem row
#define AT_TILE (64 * AT_ROWB)      // 9216 B
#define AT_BUF  (4 * AT_TILE)       // Kh,Kl,Vh,Vl
#define AT_SMEM (2 * AT_BUF)        // 73728 B double buffered

__global__ void __launch_bounds__(256, 1) attn_mma_kernel(
    const uint16_t* __restrict__ Qh, const uint16_t* __restrict__ Ql,
    const uint16_t* __restrict__ Kh, const uint16_t* __restrict__ Kl,
    const uint16_t* __restrict__ Vh, const uint16_t* __restrict__ Vl,
    uint16_t* __restrict__ Ys)
{
    extern __shared__ char smem[];
    const uint32_t sbase = smem_u32(smem);
    const int tid = threadIdx.x, wid = tid >> 5, lane = tid & 31;
    const int bh = blockIdx.y;
    const int q0 = blockIdx.x * 128;
    const size_t hb = (size_t)bh * (T_ * HS_);

    const int a_row  = ((lane >> 3) & 1) * 8 + (lane & 7);
    const int a_koff = ((lane >> 4) & 1) * 8;
    const int b_row  = ((lane >> 4) & 1) * 8 + (lane & 7);
    const int b_koff = ((lane >> 3) & 1) * 8;
    const int v_row  = lane & 15;
    const int v_coff = (lane >> 4) << 3;

    // ---- stage Q tiles, build A-frags in registers ----
    uint32_t qhf[4][4], qlf[4][4];
    {
        const uint16_t* src = Qh + hb + (size_t)q0 * HS_;
        for (int i = tid; i < 1024; i += 256) {
            int row = i >> 3, cc = i & 7;
            cp_async16(sbase + row * AT_ROWB + cc * 16, src + row * HS_ + cc * 8);
        }
        CP_COMMIT(); CP_WAIT(0); __syncthreads();
#pragma unroll
        for (int ks = 0; ks < 4; ks++)
            ldsm_x4(qhf[ks][0], qhf[ks][1], qhf[ks][2], qhf[ks][3],
                    sbase + (wid * 16 + a_row) * AT_ROWB + (ks * 16 + a_koff) * 2);
        __syncthreads();
        const uint16_t* src2 = Ql + hb + (size_t)q0 * HS_;
        for (int i = tid; i < 1024; i += 256) {
            int row = i >> 3, cc = i & 7;
            cp_async16(sbase + row * AT_ROWB + cc * 16, src2 + row * HS_ + cc * 8);
        }
        CP_COMMIT(); CP_WAIT(0); __syncthreads();
#pragma unroll
        for (int ks = 0; ks < 4; ks++)
            ldsm_x4(qlf[ks][0], qlf[ks][1], qlf[ks][2], qlf[ks][3],
                    sbase + (wid * 16 + a_row) * AT_ROWB + (ks * 16 + a_koff) * 2);
        __syncthreads();
    }

    float oc[8][4];
#pragma unroll
    for (int n = 0; n < 8; n++)
#pragma unroll
        for (int e = 0; e < 4; e++) oc[n][e] = 0.f;
    float m0 = -1e30f, m1 = -1e30f, l0 = 0.f, l1 = 0.f;
    const int wrow = q0 + wid * 16;
    const int nt = 2 * blockIdx.x + 2;

    auto load_kv = [&](int kt, int buf) {
        const int k0 = kt * 64;
        const uint16_t* srcs[4] = { Kh + hb + (size_t)k0 * HS_, Kl + hb + (size_t)k0 * HS_,
                                    Vh + hb + (size_t)k0 * HS_, Vl + hb + (size_t)k0 * HS_ };
#pragma unroll
        for (int a = 0; a < 4; a++) {
            const uint32_t d = sbase + buf * AT_BUF + a * AT_TILE;
            const uint16_t* s = srcs[a];
            for (int i = tid; i < 512; i += 256) {
                int row = i >> 3, cc = i & 7;
                cp_async16(d + row * AT_ROWB + cc * 16, s + row * HS_ + cc * 8);
            }
        }
    };

    load_kv(0, 0);
    CP_COMMIT();

    for (int kt = 0; kt < nt; kt++) {
        const int buf = kt & 1;
        const int k0 = kt * 64;
        if (kt + 1 < nt) { load_kv(kt + 1, buf ^ 1); CP_COMMIT(); CP_WAIT(1); }
        else             { CP_WAIT(0); }
        __syncthreads();

        if (k0 <= wrow + 15) {
            const uint32_t kb = sbase + buf * AT_BUF;
            float sc[8][4];
#pragma unroll
            for (int n = 0; n < 8; n++)
#pragma unroll
                for (int e = 0; e < 4; e++) sc[n][e] = 0.f;

            // ---- S = Qh*Kh + Ql*Kh + Qh*Kl ----
#pragma unroll
            for (int ks = 0; ks < 4; ks++) {
                uint32_t kf[8][2];
#pragma unroll
                for (int np = 0; np < 4; np++)
                    ldsm_x4(kf[np * 2][0], kf[np * 2][1], kf[np * 2 + 1][0], kf[np * 2 + 1][1],
                            kb + (np * 16 + b_row) * AT_ROWB + (ks * 16 + b_koff) * 2);
#pragma unroll
                for (int n = 0; n < 8; n++) {
                    mma16816(sc[n], qhf[ks][0], qhf[ks][1], qhf[ks][2], qhf[ks][3], kf[n][0], kf[n][1]);
                    mma16816(sc[n], qlf[ks][0], qlf[ks][1], qlf[ks][2], qlf[ks][3], kf[n][0], kf[n][1]);
                }
#pragma unroll
                for (int np = 0; np < 4; np++)
                    ldsm_x4(kf[np * 2][0], kf[np * 2][1], kf[np * 2 + 1][0], kf[np * 2 + 1][1],
                            kb + AT_TILE + (np * 16 + b_row) * AT_ROWB + (ks * 16 + b_koff) * 2);
#pragma unroll
                for (int n = 0; n < 8; n++)
                    mma16816(sc[n], qhf[ks][0], qhf[ks][1], qhf[ks][2], qhf[ks][3], kf[n][0], kf[n][1]);
            }

            // ---- scale + causal mask + row max ----
            const int r0g = wrow + (lane >> 2);
            const int r1g = r0g + 8;
            const int cb = k0 + (lane & 3) * 2;
            float mx0 = -1e30f, mx1 = -1e30f;
#pragma unroll
            for (int n = 0; n < 8; n++) {
                const int c0g = cb + n * 8, c1g = c0g + 1;
                sc[n][0] = (c0g > r0g) ? -1e30f : sc[n][0] * 0.125f;
                sc[n][1] = (c1g > r0g) ? -1e30f : sc[n][1] * 0.125f;
                sc[n][2] = (c0g > r1g) ? -1e30f : sc[n][2] * 0.125f;
                sc[n][3] = (c1g > r1g) ? -1e30f : sc[n][3] * 0.125f;
                mx0 = fmaxf(mx0, fmaxf(sc[n][0], sc[n][1]));
                mx1 = fmaxf(mx1, fmaxf(sc[n][2], sc[n][3]));
            }
            mx0 = fmaxf(mx0, __shfl_xor_sync(0xffffffffu, mx0, 1));
            mx0 = fmaxf(mx0, __shfl_xor_sync(0xffffffffu, mx0, 2));
            mx1 = fmaxf(mx1, __shfl_xor_sync(0xffffffffu, mx1, 1));
            mx1 = fmaxf(mx1, __shfl_xor_sync(0xffffffffu, mx1, 2));

            const float nm0 = fmaxf(m0, mx0), nm1 = fmaxf(m1, mx1);
            const float a0 = __expf(m0 - nm0), a1 = __expf(m1 - nm1);
            float s0 = 0.f, s1 = 0.f;
#pragma unroll
            for (int n = 0; n < 8; n++) {
                sc[n][0] = __expf(sc[n][0] - nm0); s0 += sc[n][0];
                sc[n][1] = __expf(sc[n][1] - nm0); s0 += sc[n][1];
                sc[n][2] = __expf(sc[n][2] - nm1); s1 += sc[n][2];
                sc[n][3] = __expf(sc[n][3] - nm1); s1 += sc[n][3];
            }
            s0 += __shfl_xor_sync(0xffffffffu, s0, 1);
            s0 += __shfl_xor_sync(0xffffffffu, s0, 2);
            s1 += __shfl_xor_sync(0xffffffffu, s1, 1);
            s1 += __shfl_xor_sync(0xffffffffu, s1, 2);
            l0 = l0 * a0 + s0; l1 = l1 * a1 + s1;
            m0 = nm0; m1 = nm1;

            // ---- rescale O ----
#pragma unroll
            for (int n = 0; n < 8; n++) {
                oc[n][0] *= a0; oc[n][1] *= a0; oc[n][2] *= a1; oc[n][3] *= a1;
            }

            // ---- pack P hi/lo A-frags ----
            uint32_t ph[4][4], pl[4][4];
#pragma unroll
            for (int j = 0; j < 4; j++) {
                split2(sc[2 * j][0],     sc[2 * j][1],     ph[j][0], pl[j][0]);
                split2(sc[2 * j][2],     sc[2 * j][3],     ph[j][1], pl[j][1]);
                split2(sc[2 * j + 1][0], sc[2 * j + 1][1], ph[j][2], pl[j][2]);
                split2(sc[2 * j + 1][2], sc[2 * j + 1][3], ph[j][3], pl[j][3]);
            }

            // ---- O += Ph*Vh + Pl*Vh + Ph*Vl ----
#pragma unroll
            for (int ks = 0; ks < 4; ks++) {
                uint32_t vf[8][2];
#pragma unroll
                for (int np = 0; np < 4; np++)
                    ldsm_x4_t(vf[np * 2][0], vf[np * 2][1], vf[np * 2 + 1][0], vf[np * 2 + 1][1],
                              kb + 2 * AT_TILE + (ks * 16 + v_row) * AT_ROWB + (np * 16 + v_coff) * 2);
#pragma unroll
                for (int n = 0; n < 8; n++) {
                    mma16816(oc[n], ph[ks][0], ph[ks][1], ph[ks][2], ph[ks][3], vf[n][0], vf[n][1]);
                    mma16816(oc[n], pl[ks][0], pl[ks][1], pl[ks][2], pl[ks][3], vf[n][0], vf[n][1]);
                }
#pragma unroll
                for (int np = 0; np < 4; np++)
                    ldsm_x4_t(vf[np * 2][0], vf[np * 2][1], vf[np * 2 + 1][0], vf[np * 2 + 1][1],
                              kb + 3 * AT_TILE + (ks * 16 + v_row) * AT_ROWB + (np * 16 + v_coff) * 2);
#pragma unroll
                for (int n = 0; n < 8; n++)
                    mma16816(oc[n], ph[ks][0], ph[ks][1], ph[ks][2], ph[ks][3], vf[n][0], vf[n][1]);
            }
        }
        __syncthreads();
    }

    // ---- epilogue: O/l, write split-y directly ----
    const float il0 = 1.0f / l0, il1 = 1.0f / l1;
    const int b = bh >> 4, h = bh & 15;
    const int t0 = q0 + wid * 16 + (lane >> 2);
    uint16_t* y0 = Ys + ((size_t)b * T_ + t0) * KP_;
    uint16_t* y1 = Ys + ((size_t)b * T_ + t0 + 8) * KP_;
    const int col0 = h * 64 + (lane & 3) * 2;
#pragma unroll
    for (int n = 0; n < 8; n++) {
        const int cc = col0 + n * 8;
        uint32_t hi, lo;
        split2(oc[n][0] * il0, oc[n][1] * il0, hi, lo);
        *(uint32_t*)(y0 + cc) = hi;
        *(uint32_t*)(y0 + cc + 1024) = lo;
        *(uint32_t*)(y0 + cc + 2048) = hi;
        split2(oc[n][2] * il1, oc[n][3] * il1, hi, lo);
        *(uint32_t*)(y1 + cc) = hi;
        *(uint32_t*)(y1 + cc + 1024) = lo;
        *(uint32_t*)(y1 + cc + 2048) = hi;
    }
}

// ======================= launch =======================
extern "C" void kernel_launch(void* const* d_in, const int* in_sizes, int n_in,
                              void* d_out, int out_size)
{
    (void)in_sizes; (void)n_in; (void)out_size;
    const float* x      = (const float*)d_in[0];
    const float* w_attn = (const float*)d_in[1];
    const float* w_proj = (const float*)d_in[2];
    float* out = (float*)d_out;

    float* qkv;
    uint16_t *xs, *was, *wps, *ys, *qh, *ql, *kh, *kl, *vh, *vl;
    cudaGetSymbolAddress((void**)&qkv, g_qkv);
    cudaGetSymbolAddress((void**)&xs,  g_xs);
    cudaGetSymbolAddress((void**)&was, g_was);
    cudaGetSymbolAddress((void**)&wps, g_wps);
    cudaGetSymbolAddress((void**)&ys,  g_ys);
    cudaGetSymbolAddress((void**)&qh,  g_qh);
    cudaGetSymbolAddress((void**)&ql,  g_ql);
    cudaGetSymbolAddress((void**)&kh,  g_kh);
    cudaGetSymbolAddress((void**)&kl,  g_kl);
    cudaGetSymbolAddress((void**)&vh,  g_vh);
    cudaGetSymbolAddress((void**)&vl,  g_vl);

    cudaFuncSetAttribute(attn_mma_kernel, cudaFuncAttributeMaxDynamicSharedMemorySize, AT_SMEM);

    // 0) split conversions of inputs
    {
        int n1 = MR_ * C_;
        split_bf16_kernel<<<(n1 + 255) / 256, 256>>>(x, xs, 1, n1);
        int n2 = TC_ * C_;
        split_bf16_kernel<<<(n2 + 255) / 256, 256>>>(w_attn, was, 0, n2);
        int n3 = C_ * C_;
        split_bf16_kernel<<<(n3 + 255) / 256, 256>>>(w_proj, wps, 0, n3);
    }
    // 1) QKV = x' @ w_attn'^T
    {
        dim3 grid(TC_ / 128, MR_ / 128);
        gemm_mma_kernel<<<grid, 256>>>(xs, was, qkv, TC_);
    }
    // 2) RoPE + head split -> split-bf16 Q/K/V
    {
        const int warps = B_ * H_ * T_;
        rope_split_kernel<<<warps * 32 / 256, 256>>>(qkv, qh, ql, kh, kl, vh, vl);
    }
    // 3) tensor-core causal flash attention (emits split-y directly)
    {
        dim3 grid(T_ / 128, B_ * H_);
        attn_mma_kernel<<<grid, 256, AT_SMEM>>>(qh, ql, kh, kl, vh, vl, ys);
    }
    // 4) out = y' @ w_proj'^T
    {
        dim3 grid(C_ / 128, MR_ / 128);
        gemm_mma_kernel<<<grid, 256>>>(ys, wps, out, C_);
    }
}

// round 8
// speedup vs baseline: 2.5380x; 1.2595x over previous
#include <cuda_runtime.h>
#include <cuda_fp16.h>
#include <math.h>
#include <stdint.h>

#define B_   2
#define T_   2048
#define C_   1024
#define H_   16
#define HS_  64
#define TC_  3072
#define MR_  4096   // B*T
#define KP2_ 2048   // fp16 2-term split K'

// ---------------- scratch (static device memory; no allocations) ----------------
__device__ float g_qkv[(size_t)MR_ * TC_];
__device__ uint16_t g_xs[(size_t)MR_ * KP2_];
__device__ uint16_t g_was[(size_t)TC_ * KP2_];
__device__ uint16_t g_wps[(size_t)C_ * KP2_];
__device__ uint16_t g_ys[(size_t)MR_ * KP2_];
// split Q (hi/lo) + rounded K,V (fp16), head-major [B*H, T, 64]
__device__ uint16_t g_qh[(size_t)B_ * H_ * T_ * HS_];
__device__ uint16_t g_ql[(size_t)B_ * H_ * T_ * HS_];
__device__ uint16_t g_kh[(size_t)B_ * H_ * T_ * HS_];
__device__ uint16_t g_vh[(size_t)B_ * H_ * T_ * HS_];

// ======================= helpers =======================
__device__ __forceinline__ uint32_t smem_u32(const void* p) {
    uint32_t a;
    asm("{ .reg .u64 t; cvta.to.shared.u64 t, %1; cvt.u32.u64 %0, t; }" : "=r"(a) : "l"(p));
    return a;
}
__device__ __forceinline__ void cp_async16(uint32_t dst, const void* src) {
    asm volatile("cp.async.cg.shared.global [%0], [%1], 16;" :: "r"(dst), "l"(src));
}
#define CP_COMMIT() asm volatile("cp.async.commit_group;" ::: "memory")
#define CP_WAIT(n)  asm volatile("cp.async.wait_group %0;" :: "n"(n) : "memory")

__device__ __forceinline__ void ldsm_x4(uint32_t& r0, uint32_t& r1, uint32_t& r2, uint32_t& r3,
                                        uint32_t addr) {
    asm volatile("ldmatrix.sync.aligned.m8n8.x4.shared.b16 {%0,%1,%2,%3}, [%4];"
                 : "=r"(r0), "=r"(r1), "=r"(r2), "=r"(r3) : "r"(addr));
}
__device__ __forceinline__ void ldsm_x4_t(uint32_t& r0, uint32_t& r1, uint32_t& r2, uint32_t& r3,
                                          uint32_t addr) {
    asm volatile("ldmatrix.sync.aligned.m8n8.x4.trans.shared.b16 {%0,%1,%2,%3}, [%4];"
                 : "=r"(r0), "=r"(r1), "=r"(r2), "=r"(r3) : "r"(addr));
}
// fp16 MMA, fp32 accumulate
__device__ __forceinline__ void mma16816(float* c, uint32_t a0, uint32_t a1, uint32_t a2,
                                         uint32_t a3, uint32_t b0, uint32_t b1) {
    asm volatile(
        "mma.sync.aligned.m16n8k16.row.col.f32.f16.f16.f32 "
        "{%0,%1,%2,%3}, {%4,%5,%6,%7}, {%8,%9}, {%0,%1,%2,%3};"
        : "+f"(c[0]), "+f"(c[1]), "+f"(c[2]), "+f"(c[3])
        : "r"(a0), "r"(a1), "r"(a2), "r"(a3), "r"(b0), "r"(b1));
}
// split two floats into packed (hi,hi) and (lo,lo) fp16x2
__device__ __forceinline__ void split2h(float a, float b, uint32_t& hi, uint32_t& lo) {
    __half ha = __float2half_rn(a), hb = __float2half_rn(b);
    float fa = __half2float(ha), fb = __half2float(hb);
    __half la = __float2half_rn(a - fa), lb = __float2half_rn(b - fb);
    hi = (uint32_t)__half_raw(ha).x | ((uint32_t)__half_raw(hb).x << 16);
    lo = (uint32_t)__half_raw(la).x | ((uint32_t)__half_raw(lb).x << 16);
}
__device__ __forceinline__ uint32_t round2h(float a, float b) {
    __half ha = __float2half_rn(a), hb = __float2half_rn(b);
    return (uint32_t)__half_raw(ha).x | ((uint32_t)__half_raw(hb).x << 16);
}

// ======================= split-fp16 conversion (inputs) =======================
// in: fp32 [R,1024]. out: fp16(u16) [R,2048]: modeA=1 -> (hi,lo), else (hi,hi)
__global__ void __launch_bounds__(256) split_f16_kernel(
    const float* __restrict__ in, uint16_t* __restrict__ out, int modeA, int total)
{
    int idx = blockIdx.x * 256 + threadIdx.x;
    if (idx >= total) return;
    const int r = idx >> 10;
    const int c = idx & 1023;
    const float v = in[idx];
    const __half hb = __float2half_rn(v);
    const float hf = __half2float(hb);
    const __half lb = __float2half_rn(v - hf);
    const uint16_t hu = __half_raw(hb).x;
    const uint16_t lu = __half_raw(lb).x;
    const size_t base = (size_t)r * KP2_ + c;
    out[base] = hu;
    out[base + 1024] = modeA ? lu : hu;
}

// ======================= mma.sync fp16 GEMM: BK=64, dynamic smem =======================
#define BK_   64
#define NKT_  (KP2_ / BK_)   // 32
#define LDA_  72             // halves per smem row (144 B)
#define GS_TILE (128 * LDA_ * 2)   // 18432 B per tile buffer
#define GS_SMEM (4 * GS_TILE)      // A0,A1,B0,B1 = 73728 B

__global__ void __launch_bounds__(256, 2) gemm_mma_kernel(
    const uint16_t* __restrict__ A, const uint16_t* __restrict__ Bm,
    float* __restrict__ C, int N)
{
    extern __shared__ char smem[];
    const uint32_t sbase = smem_u32(smem);
    const uint32_t sA[2] = { sbase,               sbase + GS_TILE };
    const uint32_t sB[2] = { sbase + 2 * GS_TILE, sbase + 3 * GS_TILE };

    const int tid  = threadIdx.x;
    const int wid  = tid >> 5;
    const int lane = tid & 31;
    const int wm = wid & 1;
    const int wn = wid >> 1;
    const int bm = blockIdx.y * 128;
    const int bn = blockIdx.x * 128;

    // loader: 2 threads per row, each 64B (4x16B)
    const int lrow = tid >> 1;
    const int lhalf = tid & 1;
    const uint16_t* Ag = A + (size_t)(bm + lrow) * KP2_ + lhalf * 32;
    const uint16_t* Bg = Bm + (size_t)(bn + lrow) * KP2_ + lhalf * 32;
    const uint32_t ldst = lrow * (LDA_ * 2) + lhalf * 64;

    const int a_row_l = ((lane >> 3) & 1) * 8 + (lane & 7);
    const int a_koff  = ((lane >> 4) & 1) * 8;
    const int b_row_l = ((lane >> 4) & 1) * 8 + (lane & 7);
    const int b_koff  = ((lane >> 3) & 1) * 8;

    float acc[4][4][4];
#pragma unroll
    for (int mi = 0; mi < 4; mi++)
#pragma unroll
        for (int ni = 0; ni < 4; ni++)
#pragma unroll
            for (int e = 0; e < 4; e++) acc[mi][ni][e] = 0.f;

    auto load_tile = [&](int kt, int buf) {
        const uint16_t* ag = Ag + (size_t)kt * BK_;
        const uint16_t* bg = Bg + (size_t)kt * BK_;
#pragma unroll
        for (int u = 0; u < 4; u++) {
            cp_async16(sA[buf] + ldst + u * 16, ag + u * 8);
            cp_async16(sB[buf] + ldst + u * 16, bg + u * 8);
        }
    };

    load_tile(0, 0);
    CP_COMMIT();

    for (int kt = 0; kt < NKT_; kt++) {
        const int buf = kt & 1;
        if (kt + 1 < NKT_) { load_tile(kt + 1, buf ^ 1); CP_COMMIT(); CP_WAIT(1); }
        else               { CP_WAIT(0); }
        __syncthreads();

#pragma unroll
        for (int ks = 0; ks < 4; ks++) {
            uint32_t a[4][4];
#pragma unroll
            for (int mi = 0; mi < 4; mi++) {
                const int row = wm * 64 + mi * 16 + a_row_l;
                ldsm_x4(a[mi][0], a[mi][1], a[mi][2], a[mi][3],
                        sA[buf] + (row * LDA_ + ks * 16 + a_koff) * 2);
            }
            uint32_t b[4][2];
#pragma unroll
            for (int np = 0; np < 2; np++) {
                const int row = wn * 32 + np * 16 + b_row_l;
                ldsm_x4(b[np * 2][0], b[np * 2][1], b[np * 2 + 1][0], b[np * 2 + 1][1],
                        sB[buf] + (row * LDA_ + ks * 16 + b_koff) * 2);
            }
#pragma unroll
            for (int mi = 0; mi < 4; mi++)
#pragma unroll
                for (int ni = 0; ni < 4; ni++)
                    mma16816(acc[mi][ni], a[mi][0], a[mi][1], a[mi][2], a[mi][3],
                             b[ni][0], b[ni][1]);
        }
        __syncthreads();
    }

    const int er = lane >> 2;
    const int ec = (lane & 3) * 2;
#pragma unroll
    for (int mi = 0; mi < 4; mi++) {
#pragma unroll
        for (int ni = 0; ni < 4; ni++) {
            const int r0 = bm + wm * 64 + mi * 16 + er;
            const int c0 = bn + wn * 32 + ni * 8 + ec;
            *(float2*)(C + (size_t)r0 * N + c0)       = make_float2(acc[mi][ni][0], acc[mi][ni][1]);
            *(float2*)(C + (size_t)(r0 + 8) * N + c0) = make_float2(acc[mi][ni][2], acc[mi][ni][3]);
        }
    }
}

// ======================= RoPE + head split -> fp16 Qh/Ql + Kh + Vh =======================
__global__ void __launch_bounds__(256) rope_split_kernel(
    const float* __restrict__ qkv,
    uint16_t* __restrict__ qh, uint16_t* __restrict__ ql,
    uint16_t* __restrict__ kh, uint16_t* __restrict__ vh)
{
    const int w    = (blockIdx.x * blockDim.x + threadIdx.x) >> 5;
    const int lane = threadIdx.x & 31;
    const int t  = w & (T_ - 1);
    const int bh = w >> 11;
    const int b  = bh >> 4;
    const int h  = bh & 15;

    const size_t row = (size_t)(b * T_ + t) * TC_;
    const int col = h * HS_ + lane * 2;

    const float2 q2 = *(const float2*)(qkv + row + col);
    const float2 k2 = *(const float2*)(qkv + row + C_ + col);
    const float2 v2 = *(const float2*)(qkv + row + 2 * C_ + col);

    const double freq = exp(-(double)lane * (9.210340371976184 / 32.0));
    const double ang  = (double)t * freq;
    double sd, cd;
    sincos(ang, &sd, &cd);
    const float c = (float)cd, s = (float)sd;

    const unsigned FULL = 0xffffffffu;
    float qp_prev = __shfl_sync(FULL, q2.y, (lane + 31) & 31);
    float qnr = q2.x * c - qp_prev * s;
    float qnr_next = __shfl_sync(FULL, qnr, (lane + 1) & 31);
    float qnp = q2.y * c + qnr_next * s;
    float kp_prev = __shfl_sync(FULL, k2.y, (lane + 31) & 31);
    float knr = k2.x * c - kp_prev * s;
    float knr_next = __shfl_sync(FULL, knr, (lane + 1) & 31);
    float knp = k2.y * c + knr_next * s;

    const size_t o = ((size_t)bh * T_ + t) * HS_ + lane * 2;
    uint32_t hi, lo;
    split2h(qnr, qnp, hi, lo);
    *(uint32_t*)(qh + o) = hi; *(uint32_t*)(ql + o) = lo;
    *(uint32_t*)(kh + o) = round2h(knr, knp);
    *(uint32_t*)(vh + o) = round2h(v2.x, v2.y);
}

// ======================= tensor-core causal flash attention (fp16) =======================
// 128 q per block, 64 kv per tile, 8 warps (16 q rows each, full kv range).
#define AT_ROWB 144                 // 72 halves * 2B per smem row
#define AT_TILE (64 * AT_ROWB)      // 9216 B
#define AT_BUF  (2 * AT_TILE)       // Kh, Vh
#define AT_SMEM (2 * AT_BUF)        // 36864 B double buffered

__global__ void __launch_bounds__(256, 1) attn_mma_kernel(
    const uint16_t* __restrict__ Qh, const uint16_t* __restrict__ Ql,
    const uint16_t* __restrict__ Kh, const uint16_t* __restrict__ Vh,
    uint16_t* __restrict__ Ys)
{
    extern __shared__ char smem[];
    const uint32_t sbase = smem_u32(smem);
    const int tid = threadIdx.x, wid = tid >> 5, lane = tid & 31;
    const int bh = blockIdx.y;
    const int q0 = blockIdx.x * 128;
    const size_t hb = (size_t)bh * (T_ * HS_);

    const int a_row  = ((lane >> 3) & 1) * 8 + (lane & 7);
    const int a_koff = ((lane >> 4) & 1) * 8;
    const int b_row  = ((lane >> 4) & 1) * 8 + (lane & 7);
    const int b_koff = ((lane >> 3) & 1) * 8;
    const int v_row  = lane & 15;
    const int v_coff = (lane >> 4) << 3;

    // ---- stage Q tiles, build A-frags in registers ----
    uint32_t qhf[4][4], qlf[4][4];
    {
        const uint16_t* src = Qh + hb + (size_t)q0 * HS_;
        for (int i = tid; i < 1024; i += 256) {
            int row = i >> 3, cc = i & 7;
            cp_async16(sbase + row * AT_ROWB + cc * 16, src + row * HS_ + cc * 8);
        }
        CP_COMMIT(); CP_WAIT(0); __syncthreads();
#pragma unroll
        for (int ks = 0; ks < 4; ks++)
            ldsm_x4(qhf[ks][0], qhf[ks][1], qhf[ks][2], qhf[ks][3],
                    sbase + (wid * 16 + a_row) * AT_ROWB + (ks * 16 + a_koff) * 2);
        __syncthreads();
        const uint16_t* src2 = Ql + hb + (size_t)q0 * HS_;
        for (int i = tid; i < 1024; i += 256) {
            int row = i >> 3, cc = i & 7;
            cp_async16(sbase + row * AT_ROWB + cc * 16, src2 + row * HS_ + cc * 8);
        }
        CP_COMMIT(); CP_WAIT(0); __syncthreads();
#pragma unroll
        for (int ks = 0; ks < 4; ks++)
            ldsm_x4(qlf[ks][0], qlf[ks][1], qlf[ks][2], qlf[ks][3],
                    sbase + (wid * 16 + a_row) * AT_ROWB + (ks * 16 + a_koff) * 2);
        __syncthreads();
    }

    float oc[8][4];
#pragma unroll
    for (int n = 0; n < 8; n++)
#pragma unroll
        for (int e = 0; e < 4; e++) oc[n][e] = 0.f;
    float m0 = -1e30f, m1 = -1e30f, l0 = 0.f, l1 = 0.f;
    const int wrow = q0 + wid * 16;
    const int nt = 2 * blockIdx.x + 2;

    auto load_kv = [&](int kt, int buf) {
        const int k0 = kt * 64;
        const uint16_t* srcs[2] = { Kh + hb + (size_t)k0 * HS_, Vh + hb + (size_t)k0 * HS_ };
#pragma unroll
        for (int a = 0; a < 2; a++) {
            const uint32_t d = sbase + buf * AT_BUF + a * AT_TILE;
            const uint16_t* s = srcs[a];
            for (int i = tid; i < 512; i += 256) {
                int row = i >> 3, cc = i & 7;
                cp_async16(d + row * AT_ROWB + cc * 16, s + row * HS_ + cc * 8);
            }
        }
    };

    load_kv(0, 0);
    CP_COMMIT();

    for (int kt = 0; kt < nt; kt++) {
        const int buf = kt & 1;
        const int k0 = kt * 64;
        if (kt + 1 < nt) { load_kv(kt + 1, buf ^ 1); CP_COMMIT(); CP_WAIT(1); }
        else             { CP_WAIT(0); }
        __syncthreads();

        if (k0 <= wrow + 15) {
            const uint32_t kb = sbase + buf * AT_BUF;
            float sc[8][4];
#pragma unroll
            for (int n = 0; n < 8; n++)
#pragma unroll
                for (int e = 0; e < 4; e++) sc[n][e] = 0.f;

            // ---- S = Qh*Kh + Ql*Kh ----
#pragma unroll
            for (int ks = 0; ks < 4; ks++) {
                uint32_t kf[8][2];
#pragma unroll
                for (int np = 0; np < 4; np++)
                    ldsm_x4(kf[np * 2][0], kf[np * 2][1], kf[np * 2 + 1][0], kf[np * 2 + 1][1],
                            kb + (np * 16 + b_row) * AT_ROWB + (ks * 16 + b_koff) * 2);
#pragma unroll
                for (int n = 0; n < 8; n++) {
                    mma16816(sc[n], qhf[ks][0], qhf[ks][1], qhf[ks][2], qhf[ks][3], kf[n][0], kf[n][1]);
                    mma16816(sc[n], qlf[ks][0], qlf[ks][1], qlf[ks][2], qlf[ks][3], kf[n][0], kf[n][1]);
                }
            }

            // ---- scale + causal mask + row max ----
            const int r0g = wrow + (lane >> 2);
            const int r1g = r0g + 8;
            const int cb = k0 + (lane & 3) * 2;
            float mx0 = -1e30f, mx1 = -1e30f;
#pragma unroll
            for (int n = 0; n < 8; n++) {
                const int c0g = cb + n * 8, c1g = c0g + 1;
                sc[n][0] = (c0g > r0g) ? -1e30f : sc[n][0] * 0.125f;
                sc[n][1] = (c1g > r0g) ? -1e30f : sc[n][1] * 0.125f;
                sc[n][2] = (c0g > r1g) ? -1e30f : sc[n][2] * 0.125f;
                sc[n][3] = (c1g > r1g) ? -1e30f : sc[n][3] * 0.125f;
                mx0 = fmaxf(mx0, fmaxf(sc[n][0], sc[n][1]));
                mx1 = fmaxf(mx1, fmaxf(sc[n][2], sc[n][3]));
            }
            mx0 = fmaxf(mx0, __shfl_xor_sync(0xffffffffu, mx0, 1));
            mx0 = fmaxf(mx0, __shfl_xor_sync(0xffffffffu, mx0, 2));
            mx1 = fmaxf(mx1, __shfl_xor_sync(0xffffffffu, mx1, 1));
            mx1 = fmaxf(mx1, __shfl_xor_sync(0xffffffffu, mx1, 2));

            const float nm0 = fmaxf(m0, mx0), nm1 = fmaxf(m1, mx1);
            const float a0 = __expf(m0 - nm0), a1 = __expf(m1 - nm1);
            float s0 = 0.f, s1 = 0.f;
#pragma unroll
            for (int n = 0; n < 8; n++) {
                sc[n][0] = __expf(sc[n][0] - nm0); s0 += sc[n][0];
                sc[n][1] = __expf(sc[n][1] - nm0); s0 += sc[n][1];
                sc[n][2] = __expf(sc[n][2] - nm1); s1 += sc[n][2];
                sc[n][3] = __expf(sc[n][3] - nm1); s1 += sc[n][3];
            }
            s0 += __shfl_xor_sync(0xffffffffu, s0, 1);
            s0 += __shfl_xor_sync(0xffffffffu, s0, 2);
            s1 += __shfl_xor_sync(0xffffffffu, s1, 1);
            s1 += __shfl_xor_sync(0xffffffffu, s1, 2);
            l0 = l0 * a0 + s0; l1 = l1 * a1 + s1;
            m0 = nm0; m1 = nm1;

            // ---- rescale O ----
#pragma unroll
            for (int n = 0; n < 8; n++) {
                oc[n][0] *= a0; oc[n][1] *= a0; oc[n][2] *= a1; oc[n][3] *= a1;
            }

            // ---- pack P hi/lo A-frags ----
            uint32_t ph[4][4], pl[4][4];
#pragma unroll
            for (int j = 0; j < 4; j++) {
                split2h(sc[2 * j][0],     sc[2 * j][1],     ph[j][0], pl[j][0]);
                split2h(sc[2 * j][2],     sc[2 * j][3],     ph[j][1], pl[j][1]);
                split2h(sc[2 * j + 1][0], sc[2 * j + 1][1], ph[j][2], pl[j][2]);
                split2h(sc[2 * j + 1][2], sc[2 * j + 1][3], ph[j][3], pl[j][3]);
            }

            // ---- O += Ph*Vh + Pl*Vh ----
#pragma unroll
            for (int ks = 0; ks < 4; ks++) {
                uint32_t vf[8][2];
#pragma unroll
                for (int np = 0; np < 4; np++)
                    ldsm_x4_t(vf[np * 2][0], vf[np * 2][1], vf[np * 2 + 1][0], vf[np * 2 + 1][1],
                              kb + AT_TILE + (ks * 16 + v_row) * AT_ROWB + (np * 16 + v_coff) * 2);
#pragma unroll
                for (int n = 0; n < 8; n++) {
                    mma16816(oc[n], ph[ks][0], ph[ks][1], ph[ks][2], ph[ks][3], vf[n][0], vf[n][1]);
                    mma16816(oc[n], pl[ks][0], pl[ks][1], pl[ks][2], pl[ks][3], vf[n][0], vf[n][1]);
                }
            }
        }
        __syncthreads();
    }

    // ---- epilogue: O/l, write split-y (hi,lo) directly ----
    const float il0 = 1.0f / l0, il1 = 1.0f / l1;
    const int b = bh >> 4, h = bh & 15;
    const int t0 = q0 + wid * 16 + (lane >> 2);
    uint16_t* y0 = Ys + ((size_t)b * T_ + t0) * KP2_;
    uint16_t* y1 = Ys + ((size_t)b * T_ + t0 + 8) * KP2_;
    const int col0 = h * 64 + (lane & 3) * 2;
#pragma unroll
    for (int n = 0; n < 8; n++) {
        const int cc = col0 + n * 8;
        uint32_t hi, lo;
        split2h(oc[n][0] * il0, oc[n][1] * il0, hi, lo);
        *(uint32_t*)(y0 + cc) = hi;
        *(uint32_t*)(y0 + cc + 1024) = lo;
        split2h(oc[n][2] * il1, oc[n][3] * il1, hi, lo);
        *(uint32_t*)(y1 + cc) = hi;
        *(uint32_t*)(y1 + cc + 1024) = lo;
    }
}

// ======================= launch =======================
extern "C" void kernel_launch(void* const* d_in, const int* in_sizes, int n_in,
                              void* d_out, int out_size)
{
    (void)in_sizes; (void)n_in; (void)out_size;
    const float* x      = (const float*)d_in[0];
    const float* w_attn = (const float*)d_in[1];
    const float* w_proj = (const float*)d_in[2];
    float* out = (float*)d_out;

    float* qkv;
    uint16_t *xs, *was, *wps, *ys, *qh, *ql, *kh, *vh;
    cudaGetSymbolAddress((void**)&qkv, g_qkv);
    cudaGetSymbolAddress((void**)&xs,  g_xs);
    cudaGetSymbolAddress((void**)&was, g_was);
    cudaGetSymbolAddress((void**)&wps, g_wps);
    cudaGetSymbolAddress((void**)&ys,  g_ys);
    cudaGetSymbolAddress((void**)&qh,  g_qh);
    cudaGetSymbolAddress((void**)&ql,  g_ql);
    cudaGetSymbolAddress((void**)&kh,  g_kh);
    cudaGetSymbolAddress((void**)&vh,  g_vh);

    cudaFuncSetAttribute(gemm_mma_kernel, cudaFuncAttributeMaxDynamicSharedMemorySize, GS_SMEM);
    cudaFuncSetAttribute(attn_mma_kernel, cudaFuncAttributeMaxDynamicSharedMemorySize, AT_SMEM);

    // 0) split conversions of inputs
    {
        int n1 = MR_ * C_;
        split_f16_kernel<<<(n1 + 255) / 256, 256>>>(x, xs, 1, n1);
        int n2 = TC_ * C_;
        split_f16_kernel<<<(n2 + 255) / 256, 256>>>(w_attn, was, 0, n2);
        int n3 = C_ * C_;
        split_f16_kernel<<<(n3 + 255) / 256, 256>>>(w_proj, wps, 0, n3);
    }
    // 1) QKV = x' @ w_attn'^T
    {
        dim3 grid(TC_ / 128, MR_ / 128);
        gemm_mma_kernel<<<grid, 256, GS_SMEM>>>(xs, was, qkv, TC_);
    }
    // 2) RoPE + head split -> fp16 Qh/Ql, Kh, Vh
    {
        const int warps = B_ * H_ * T_;
        rope_split_kernel<<<warps * 32 / 256, 256>>>(qkv, qh, ql, kh, vh);
    }
    // 3) tensor-core causal flash attention (emits split-y directly)
    {
        dim3 grid(T_ / 128, B_ * H_);
        attn_mma_kernel<<<grid, 256, AT_SMEM>>>(qh, ql, kh, vh, ys);
    }
    // 4) out = y' @ w_proj'^T
    {
        dim3 grid(C_ / 128, MR_ / 128);
        gemm_mma_kernel<<<grid, 256, GS_SMEM>>>(ys, wps, out, C_);
    }
}

// round 9
// speedup vs baseline: 3.3837x; 1.3332x over previous
#include <cuda_runtime.h>
#include <cuda_fp16.h>
#include <math.h>
#include <stdint.h>

#define B_   2
#define T_   2048
#define C_   1024
#define H_   16
#define HS_  64
#define TC_  3072
#define MR_  4096   // B*T
#define KP2_ 2048   // fp16 2-term split K'

// ---------------- scratch (static device memory; no allocations) ----------------
__device__ float g_qkv[(size_t)MR_ * TC_];
__device__ uint16_t g_xs[(size_t)MR_ * KP2_];
__device__ uint16_t g_was[(size_t)TC_ * KP2_];
__device__ uint16_t g_wps[(size_t)C_ * KP2_];
__device__ uint16_t g_ys[(size_t)MR_ * KP2_];
__device__ uint16_t g_qh[(size_t)B_ * H_ * T_ * HS_];
__device__ uint16_t g_ql[(size_t)B_ * H_ * T_ * HS_];
__device__ uint16_t g_kh[(size_t)B_ * H_ * T_ * HS_];
__device__ uint16_t g_vh[(size_t)B_ * H_ * T_ * HS_];
__device__ float2 g_rope[(size_t)T_ * 32];

// ======================= helpers =======================
__device__ __forceinline__ uint32_t smem_u32(const void* p) {
    uint32_t a;
    asm("{ .reg .u64 t; cvta.to.shared.u64 t, %1; cvt.u32.u64 %0, t; }" : "=r"(a) : "l"(p));
    return a;
}
__device__ __forceinline__ void cp_async16(uint32_t dst, const void* src) {
    asm volatile("cp.async.cg.shared.global [%0], [%1], 16;" :: "r"(dst), "l"(src));
}
#define CP_COMMIT() asm volatile("cp.async.commit_group;" ::: "memory")
#define CP_WAIT(n)  asm volatile("cp.async.wait_group %0;" :: "n"(n) : "memory")

__device__ __forceinline__ void ldsm_x4(uint32_t& r0, uint32_t& r1, uint32_t& r2, uint32_t& r3,
                                        uint32_t addr) {
    asm volatile("ldmatrix.sync.aligned.m8n8.x4.shared.b16 {%0,%1,%2,%3}, [%4];"
                 : "=r"(r0), "=r"(r1), "=r"(r2), "=r"(r3) : "r"(addr));
}
__device__ __forceinline__ void ldsm_x4_t(uint32_t& r0, uint32_t& r1, uint32_t& r2, uint32_t& r3,
                                          uint32_t addr) {
    asm volatile("ldmatrix.sync.aligned.m8n8.x4.trans.shared.b16 {%0,%1,%2,%3}, [%4];"
                 : "=r"(r0), "=r"(r1), "=r"(r2), "=r"(r3) : "r"(addr));
}
__device__ __forceinline__ void mma16816(float* c, uint32_t a0, uint32_t a1, uint32_t a2,
                                         uint32_t a3, uint32_t b0, uint32_t b1) {
    asm volatile(
        "mma.sync.aligned.m16n8k16.row.col.f32.f16.f16.f32 "
        "{%0,%1,%2,%3}, {%4,%5,%6,%7}, {%8,%9}, {%0,%1,%2,%3};"
        : "+f"(c[0]), "+f"(c[1]), "+f"(c[2]), "+f"(c[3])
        : "r"(a0), "r"(a1), "r"(a2), "r"(a3), "r"(b0), "r"(b1));
}
__device__ __forceinline__ void split2h(float a, float b, uint32_t& hi, uint32_t& lo) {
    __half ha = __float2half_rn(a), hb = __float2half_rn(b);
    float fa = __half2float(ha), fb = __half2float(hb);
    __half la = __float2half_rn(a - fa), lb = __float2half_rn(b - fb);
    hi = (uint32_t)__half_raw(ha).x | ((uint32_t)__half_raw(hb).x << 16);
    lo = (uint32_t)__half_raw(la).x | ((uint32_t)__half_raw(lb).x << 16);
}
__device__ __forceinline__ uint32_t round2h(float a, float b) {
    __half ha = __float2half_rn(a), hb = __float2half_rn(b);
    return (uint32_t)__half_raw(ha).x | ((uint32_t)__half_raw(hb).x << 16);
}

// ======================= split-fp16 conversion (inputs) =======================
__global__ void __launch_bounds__(256) split_f16_kernel(
    const float* __restrict__ in, uint16_t* __restrict__ out, int modeA, int total)
{
    int idx = blockIdx.x * 256 + threadIdx.x;
    if (idx >= total) return;
    const int r = idx >> 10;
    const int c = idx & 1023;
    const float v = in[idx];
    const __half hb = __float2half_rn(v);
    const float hf = __half2float(hb);
    const __half lb = __float2half_rn(v - hf);
    const uint16_t hu = __half_raw(hb).x;
    const uint16_t lu = __half_raw(lb).x;
    const size_t base = (size_t)r * KP2_ + c;
    out[base] = hu;
    out[base + 1024] = modeA ? lu : hu;
}

// ======================= fp16 GEMM: BK=64, 3-stage pipeline, 1 sync/iter ===========
#define BK_   64
#define NKT_  (KP2_ / BK_)   // 32
#define LDA_  72             // halves per smem row (144 B)
#define GS_TILE 18432        // 128 * 72 * 2
#define GS_STG  (2 * GS_TILE)   // A + B per stage = 36864
#define GS_SMEM (3 * GS_STG)    // 110592

__global__ void __launch_bounds__(256, 2) gemm_mma_kernel(
    const uint16_t* __restrict__ A, const uint16_t* __restrict__ Bm,
    float* __restrict__ C, int N)
{
    extern __shared__ char smem[];
    const uint32_t sbase = smem_u32(smem);

    const int tid  = threadIdx.x;
    const int wid  = tid >> 5;
    const int lane = tid & 31;
    const int wm = wid & 1;
    const int wn = wid >> 1;
    const int bm = blockIdx.y * 128;
    const int bn = blockIdx.x * 128;

    const int lrow = tid >> 1;
    const int lhalf = tid & 1;
    const uint16_t* Ag = A + (size_t)(bm + lrow) * KP2_ + lhalf * 32;
    const uint16_t* Bg = Bm + (size_t)(bn + lrow) * KP2_ + lhalf * 32;
    const uint32_t ldst = lrow * (LDA_ * 2) + lhalf * 64;

    const int a_row_l = ((lane >> 3) & 1) * 8 + (lane & 7);
    const int a_koff  = ((lane >> 4) & 1) * 8;
    const int b_row_l = ((lane >> 4) & 1) * 8 + (lane & 7);
    const int b_koff  = ((lane >> 3) & 1) * 8;

    float acc[4][4][4];
#pragma unroll
    for (int mi = 0; mi < 4; mi++)
#pragma unroll
        for (int ni = 0; ni < 4; ni++)
#pragma unroll
            for (int e = 0; e < 4; e++) acc[mi][ni][e] = 0.f;

    auto load_tile = [&](int kt, int stg) {
        const uint32_t dA = sbase + stg * GS_STG;
        const uint32_t dB = dA + GS_TILE;
        const uint16_t* ag = Ag + (size_t)kt * BK_;
        const uint16_t* bg = Bg + (size_t)kt * BK_;
#pragma unroll
        for (int u = 0; u < 4; u++) {
            cp_async16(dA + ldst + u * 16, ag + u * 8);
            cp_async16(dB + ldst + u * 16, bg + u * 8);
        }
    };

    load_tile(0, 0); CP_COMMIT();
    load_tile(1, 1); CP_COMMIT();

    int stg = 0;
    for (int kt = 0; kt < NKT_; kt++) {
        if (kt == NKT_ - 1) { CP_WAIT(0); } else { CP_WAIT(1); }
        __syncthreads();
        if (kt + 2 < NKT_) {
            int ns = stg + 2; if (ns >= 3) ns -= 3;
            load_tile(kt + 2, ns);
            CP_COMMIT();
        }
        const uint32_t sA = sbase + stg * GS_STG;
        const uint32_t sB = sA + GS_TILE;

#pragma unroll
        for (int ks = 0; ks < 4; ks++) {
            uint32_t a[4][4];
#pragma unroll
            for (int mi = 0; mi < 4; mi++) {
                const int row = wm * 64 + mi * 16 + a_row_l;
                ldsm_x4(a[mi][0], a[mi][1], a[mi][2], a[mi][3],
                        sA + (row * LDA_ + ks * 16 + a_koff) * 2);
            }
            uint32_t b[4][2];
#pragma unroll
            for (int np = 0; np < 2; np++) {
                const int row = wn * 32 + np * 16 + b_row_l;
                ldsm_x4(b[np * 2][0], b[np * 2][1], b[np * 2 + 1][0], b[np * 2 + 1][1],
                        sB + (row * LDA_ + ks * 16 + b_koff) * 2);
            }
#pragma unroll
            for (int mi = 0; mi < 4; mi++)
#pragma unroll
                for (int ni = 0; ni < 4; ni++)
                    mma16816(acc[mi][ni], a[mi][0], a[mi][1], a[mi][2], a[mi][3],
                             b[ni][0], b[ni][1]);
        }
        stg++; if (stg == 3) stg = 0;
    }

    const int er = lane >> 2;
    const int ec = (lane & 3) * 2;
#pragma unroll
    for (int mi = 0; mi < 4; mi++) {
#pragma unroll
        for (int ni = 0; ni < 4; ni++) {
            const int r0 = bm + wm * 64 + mi * 16 + er;
            const int c0 = bn + wn * 32 + ni * 8 + ec;
            *(float2*)(C + (size_t)r0 * N + c0)       = make_float2(acc[mi][ni][0], acc[mi][ni][1]);
            *(float2*)(C + (size_t)(r0 + 8) * N + c0) = make_float2(acc[mi][ni][2], acc[mi][ni][3]);
        }
    }
}

// ======================= RoPE trig table (fp64, tiny) =======================
__global__ void __launch_bounds__(256) rope_table_kernel(float2* __restrict__ tab)
{
    const int idx = blockIdx.x * 256 + threadIdx.x;   // t*32 + lane
    if (idx >= T_ * 32) return;
    const int t = idx >> 5, lane = idx & 31;
    const double freq = exp(-(double)lane * (9.210340371976184 / 32.0));
    double sd, cd;
    sincos((double)t * freq, &sd, &cd);
    tab[idx] = make_float2((float)cd, (float)sd);
}

// ======================= RoPE + head split -> fp16 Qh/Ql + Kh + Vh ==============
__global__ void __launch_bounds__(256) rope_split_kernel(
    const float* __restrict__ qkv, const float2* __restrict__ tab,
    uint16_t* __restrict__ qh, uint16_t* __restrict__ ql,
    uint16_t* __restrict__ kh, uint16_t* __restrict__ vh)
{
    const int w    = (blockIdx.x * blockDim.x + threadIdx.x) >> 5;
    const int lane = threadIdx.x & 31;
    const int t  = w & (T_ - 1);
    const int bh = w >> 11;
    const int b  = bh >> 4;
    const int h  = bh & 15;

    const size_t row = (size_t)(b * T_ + t) * TC_;
    const int col = h * HS_ + lane * 2;

    const float2 q2 = *(const float2*)(qkv + row + col);
    const float2 k2 = *(const float2*)(qkv + row + C_ + col);
    const float2 v2 = *(const float2*)(qkv + row + 2 * C_ + col);

    const float2 cs = tab[t * 32 + lane];
    const float c = cs.x, s = cs.y;

    const unsigned FULL = 0xffffffffu;
    float qp_prev = __shfl_sync(FULL, q2.y, (lane + 31) & 31);
    float qnr = q2.x * c - qp_prev * s;
    float qnr_next = __shfl_sync(FULL, qnr, (lane + 1) & 31);
    float qnp = q2.y * c + qnr_next * s;
    float kp_prev = __shfl_sync(FULL, k2.y, (lane + 31) & 31);
    float knr = k2.x * c - kp_prev * s;
    float knr_next = __shfl_sync(FULL, knr, (lane + 1) & 31);
    float knp = k2.y * c + knr_next * s;

    const size_t o = ((size_t)bh * T_ + t) * HS_ + lane * 2;
    uint32_t hi, lo;
    split2h(qnr, qnp, hi, lo);
    *(uint32_t*)(qh + o) = hi; *(uint32_t*)(ql + o) = lo;
    *(uint32_t*)(kh + o) = round2h(knr, knp);
    *(uint32_t*)(vh + o) = round2h(v2.x, v2.y);
}

// ======================= tensor-core causal flash attention (fp16) ==============
// 128 q per block, 64 kv per tile, 3-stage pipeline, 1 sync/iter.
#define AT_ROWB 144                 // 72 halves * 2B per smem row
#define AT_TILE (64 * AT_ROWB)      // 9216 B (one K or V tile)
#define AT_BUF  (2 * AT_TILE)       // K + V per stage = 18432
#define AT_SMEM (3 * AT_BUF)        // 55296

__global__ void __launch_bounds__(256, 1) attn_mma_kernel(
    const uint16_t* __restrict__ Qh, const uint16_t* __restrict__ Ql,
    const uint16_t* __restrict__ Kh, const uint16_t* __restrict__ Vh,
    uint16_t* __restrict__ Ys)
{
    extern __shared__ char smem[];
    const uint32_t sbase = smem_u32(smem);
    const int tid = threadIdx.x, wid = tid >> 5, lane = tid & 31;
    const int bh = blockIdx.y;
    const int q0 = blockIdx.x * 128;
    const size_t hb = (size_t)bh * (T_ * HS_);

    const int a_row  = ((lane >> 3) & 1) * 8 + (lane & 7);
    const int a_koff = ((lane >> 4) & 1) * 8;
    const int b_row  = ((lane >> 4) & 1) * 8 + (lane & 7);
    const int b_koff = ((lane >> 3) & 1) * 8;
    const int v_row  = lane & 15;
    const int v_coff = (lane >> 4) << 3;

    // ---- stage Qh (stage0 area) + Ql (stage1 area) in ONE round ----
    uint32_t qhf[4][4], qlf[4][4];
    {
        const uint16_t* srch = Qh + hb + (size_t)q0 * HS_;
        const uint16_t* srcl = Ql + hb + (size_t)q0 * HS_;
        for (int i = tid; i < 1024; i += 256) {
            int row = i >> 3, cc = i & 7;
            cp_async16(sbase + row * AT_ROWB + cc * 16, srch + row * HS_ + cc * 8);
            cp_async16(sbase + AT_BUF + row * AT_ROWB + cc * 16, srcl + row * HS_ + cc * 8);
        }
        CP_COMMIT(); CP_WAIT(0); __syncthreads();
#pragma unroll
        for (int ks = 0; ks < 4; ks++) {
            ldsm_x4(qhf[ks][0], qhf[ks][1], qhf[ks][2], qhf[ks][3],
                    sbase + (wid * 16 + a_row) * AT_ROWB + (ks * 16 + a_koff) * 2);
            ldsm_x4(qlf[ks][0], qlf[ks][1], qlf[ks][2], qlf[ks][3],
                    sbase + AT_BUF + (wid * 16 + a_row) * AT_ROWB + (ks * 16 + a_koff) * 2);
        }
        __syncthreads();
    }

    float oc[8][4];
#pragma unroll
    for (int n = 0; n < 8; n++)
#pragma unroll
        for (int e = 0; e < 4; e++) oc[n][e] = 0.f;
    float m0 = -1e30f, m1 = -1e30f, l0 = 0.f, l1 = 0.f;
    const int wrow = q0 + wid * 16;
    const int nt = 2 * blockIdx.x + 2;

    auto load_kv = [&](int kt, int stg) {
        const int k0 = kt * 64;
        const uint32_t dK = sbase + stg * AT_BUF;
        const uint32_t dV = dK + AT_TILE;
        const uint16_t* sk = Kh + hb + (size_t)k0 * HS_;
        const uint16_t* sv = Vh + hb + (size_t)k0 * HS_;
        for (int i = tid; i < 512; i += 256) {
            int row = i >> 3, cc = i & 7;
            cp_async16(dK + row * AT_ROWB + cc * 16, sk + row * HS_ + cc * 8);
            cp_async16(dV + row * AT_ROWB + cc * 16, sv + row * HS_ + cc * 8);
        }
    };

    load_kv(0, 0); CP_COMMIT();
    load_kv(1, 1); CP_COMMIT();

    int stg = 0;
    for (int kt = 0; kt < nt; kt++) {
        const int k0 = kt * 64;
        if (kt == nt - 1) { CP_WAIT(0); } else { CP_WAIT(1); }
        __syncthreads();
        if (kt + 2 < nt) {
            int ns = stg + 2; if (ns >= 3) ns -= 3;
            load_kv(kt + 2, ns);
            CP_COMMIT();
        }

        if (k0 <= wrow + 15) {
            const uint32_t kb = sbase + stg * AT_BUF;
            float sc[8][4];
#pragma unroll
            for (int n = 0; n < 8; n++)
#pragma unroll
                for (int e = 0; e < 4; e++) sc[n][e] = 0.f;

            // ---- S = Qh*Kh + Ql*Kh ----
#pragma unroll
            for (int ks = 0; ks < 4; ks++) {
                uint32_t kf[8][2];
#pragma unroll
                for (int np = 0; np < 4; np++)
                    ldsm_x4(kf[np * 2][0], kf[np * 2][1], kf[np * 2 + 1][0], kf[np * 2 + 1][1],
                            kb + (np * 16 + b_row) * AT_ROWB + (ks * 16 + b_koff) * 2);
#pragma unroll
                for (int n = 0; n < 8; n++) {
                    mma16816(sc[n], qhf[ks][0], qhf[ks][1], qhf[ks][2], qhf[ks][3], kf[n][0], kf[n][1]);
                    mma16816(sc[n], qlf[ks][0], qlf[ks][1], qlf[ks][2], qlf[ks][3], kf[n][0], kf[n][1]);
                }
            }

            // ---- scale + causal mask + row max ----
            const int r0g = wrow + (lane >> 2);
            const int r1g = r0g + 8;
            const int cb = k0 + (lane & 3) * 2;
            float mx0 = -1e30f, mx1 = -1e30f;
#pragma unroll
            for (int n = 0; n < 8; n++) {
                const int c0g = cb + n * 8, c1g = c0g + 1;
                sc[n][0] = (c0g > r0g) ? -1e30f : sc[n][0] * 0.125f;
                sc[n][1] = (c1g > r0g) ? -1e30f : sc[n][1] * 0.125f;
                sc[n][2] = (c0g > r1g) ? -1e30f : sc[n][2] * 0.125f;
                sc[n][3] = (c1g > r1g) ? -1e30f : sc[n][3] * 0.125f;
                mx0 = fmaxf(mx0, fmaxf(sc[n][0], sc[n][1]));
                mx1 = fmaxf(mx1, fmaxf(sc[n][2], sc[n][3]));
            }
            mx0 = fmaxf(mx0, __shfl_xor_sync(0xffffffffu, mx0, 1));
            mx0 = fmaxf(mx0, __shfl_xor_sync(0xffffffffu, mx0, 2));
            mx1 = fmaxf(mx1, __shfl_xor_sync(0xffffffffu, mx1, 1));
            mx1 = fmaxf(mx1, __shfl_xor_sync(0xffffffffu, mx1, 2));

            const float nm0 = fmaxf(m0, mx0), nm1 = fmaxf(m1, mx1);
            const float a0 = __expf(m0 - nm0), a1 = __expf(m1 - nm1);
            float s0 = 0.f, s1 = 0.f;
#pragma unroll
            for (int n = 0; n < 8; n++) {
                sc[n][0] = __expf(sc[n][0] - nm0); s0 += sc[n][0];
                sc[n][1] = __expf(sc[n][1] - nm0); s0 += sc[n][1];
                sc[n][2] = __expf(sc[n][2] - nm1); s1 += sc[n][2];
                sc[n][3] = __expf(sc[n][3] - nm1); s1 += sc[n][3];
            }
            s0 += __shfl_xor_sync(0xffffffffu, s0, 1);
            s0 += __shfl_xor_sync(0xffffffffu, s0, 2);
            s1 += __shfl_xor_sync(0xffffffffu, s1, 1);
            s1 += __shfl_xor_sync(0xffffffffu, s1, 2);
            l0 = l0 * a0 + s0; l1 = l1 * a1 + s1;
            m0 = nm0; m1 = nm1;

#pragma unroll
            for (int n = 0; n < 8; n++) {
                oc[n][0] *= a0; oc[n][1] *= a0; oc[n][2] *= a1; oc[n][3] *= a1;
            }

            // ---- pack P hi/lo A-frags ----
            uint32_t ph[4][4], pl[4][4];
#pragma unroll
            for (int j = 0; j < 4; j++) {
                split2h(sc[2 * j][0],     sc[2 * j][1],     ph[j][0], pl[j][0]);
                split2h(sc[2 * j][2],     sc[2 * j][3],     ph[j][1], pl[j][1]);
                split2h(sc[2 * j + 1][0], sc[2 * j + 1][1], ph[j][2], pl[j][2]);
                split2h(sc[2 * j + 1][2], sc[2 * j + 1][3], ph[j][3], pl[j][3]);
            }

            // ---- O += Ph*Vh + Pl*Vh ----
#pragma unroll
            for (int ks = 0; ks < 4; ks++) {
                uint32_t vf[8][2];
#pragma unroll
                for (int np = 0; np < 4; np++)
                    ldsm_x4_t(vf[np * 2][0], vf[np * 2][1], vf[np * 2 + 1][0], vf[np * 2 + 1][1],
                              kb + AT_TILE + (ks * 16 + v_row) * AT_ROWB + (np * 16 + v_coff) * 2);
#pragma unroll
                for (int n = 0; n < 8; n++) {
                    mma16816(oc[n], ph[ks][0], ph[ks][1], ph[ks][2], ph[ks][3], vf[n][0], vf[n][1]);
                    mma16816(oc[n], pl[ks][0], pl[ks][1], pl[ks][2], pl[ks][3], vf[n][0], vf[n][1]);
                }
            }
        }
        stg++; if (stg == 3) stg = 0;
    }

    // ---- epilogue: O/l, write split-y (hi,lo) directly ----
    const float il0 = 1.0f / l0, il1 = 1.0f / l1;
    const int b = bh >> 4, h = bh & 15;
    const int t0 = q0 + wid * 16 + (lane >> 2);
    uint16_t* y0 = Ys + ((size_t)b * T_ + t0) * KP2_;
    uint16_t* y1 = Ys + ((size_t)b * T_ + t0 + 8) * KP2_;
    const int col0 = h * 64 + (lane & 3) * 2;
#pragma unroll
    for (int n = 0; n < 8; n++) {
        const int cc = col0 + n * 8;
        uint32_t hi, lo;
        split2h(oc[n][0] * il0, oc[n][1] * il0, hi, lo);
        *(uint32_t*)(y0 + cc) = hi;
        *(uint32_t*)(y0 + cc + 1024) = lo;
        split2h(oc[n][2] * il1, oc[n][3] * il1, hi, lo);
        *(uint32_t*)(y1 + cc) = hi;
        *(uint32_t*)(y1 + cc + 1024) = lo;
    }
}

// ======================= launch =======================
extern "C" void kernel_launch(void* const* d_in, const int* in_sizes, int n_in,
                              void* d_out, int out_size)
{
    (void)in_sizes; (void)n_in; (void)out_size;
    const float* x      = (const float*)d_in[0];
    const float* w_attn = (const float*)d_in[1];
    const float* w_proj = (const float*)d_in[2];
    float* out = (float*)d_out;

    float* qkv;
    float2* tab;
    uint16_t *xs, *was, *wps, *ys, *qh, *ql, *kh, *vh;
    cudaGetSymbolAddress((void**)&qkv, g_qkv);
    cudaGetSymbolAddress((void**)&tab, g_rope);
    cudaGetSymbolAddress((void**)&xs,  g_xs);
    cudaGetSymbolAddress((void**)&was, g_was);
    cudaGetSymbolAddress((void**)&wps, g_wps);
    cudaGetSymbolAddress((void**)&ys,  g_ys);
    cudaGetSymbolAddress((void**)&qh,  g_qh);
    cudaGetSymbolAddress((void**)&ql,  g_ql);
    cudaGetSymbolAddress((void**)&kh,  g_kh);
    cudaGetSymbolAddress((void**)&vh,  g_vh);

    cudaFuncSetAttribute(gemm_mma_kernel, cudaFuncAttributeMaxDynamicSharedMemorySize, GS_SMEM);
    cudaFuncSetAttribute(attn_mma_kernel, cudaFuncAttributeMaxDynamicSharedMemorySize, AT_SMEM);

    // 0) rope table + split conversions of inputs
    rope_table_kernel<<<(T_ * 32 + 255) / 256, 256>>>(tab);
    {
        int n1 = MR_ * C_;
        split_f16_kernel<<<(n1 + 255) / 256, 256>>>(x, xs, 1, n1);
        int n2 = TC_ * C_;
        split_f16_kernel<<<(n2 + 255) / 256, 256>>>(w_attn, was, 0, n2);
        int n3 = C_ * C_;
        split_f16_kernel<<<(n3 + 255) / 256, 256>>>(w_proj, wps, 0, n3);
    }
    // 1) QKV = x' @ w_attn'^T
    {
        dim3 grid(TC_ / 128, MR_ / 128);
        gemm_mma_kernel<<<grid, 256, GS_SMEM>>>(xs, was, qkv, TC_);
    }
    // 2) RoPE + head split -> fp16 Qh/Ql, Kh, Vh
    {
        const int warps = B_ * H_ * T_;
        rope_split_kernel<<<warps * 32 / 256, 256>>>(qkv, tab, qh, ql, kh, vh);
    }
    // 3) tensor-core causal flash attention (emits split-y directly)
    {
        dim3 grid(T_ / 128, B_ * H_);
        attn_mma_kernel<<<grid, 256, AT_SMEM>>>(qh, ql, kh, vh, ys);
    }
    // 4) out = y' @ w_proj'^T
    {
        dim3 grid(C_ / 128, MR_ / 128);
        gemm_mma_kernel<<<grid, 256, GS_SMEM>>>(ys, wps, out, C_);
    }
}

// round 10
// speedup vs baseline: 3.4803x; 1.0285x over previous
#include <cuda_runtime.h>
#include <cuda_fp16.h>
#include <math.h>
#include <stdint.h>

#define B_   2
#define T_   2048
#define C_   1024
#define H_   16
#define HS_  64
#define TC_  3072
#define MR_  4096   // B*T
#define KP2_ 2048   // fp16 2-term split K'

// ---------------- scratch (static device memory; no allocations) ----------------
__device__ float g_qkv[(size_t)MR_ * TC_];
__device__ uint16_t g_xs[(size_t)MR_ * KP2_];
__device__ uint16_t g_was[(size_t)TC_ * KP2_];
__device__ uint16_t g_wps[(size_t)C_ * KP2_];
__device__ uint16_t g_ys[(size_t)MR_ * KP2_];
__device__ uint16_t g_qh[(size_t)B_ * H_ * T_ * HS_];
__device__ uint16_t g_ql[(size_t)B_ * H_ * T_ * HS_];
__device__ uint16_t g_kh[(size_t)B_ * H_ * T_ * HS_];
__device__ uint16_t g_vh[(size_t)B_ * H_ * T_ * HS_];
__device__ float2 g_rope[(size_t)T_ * 32];

// ======================= helpers =======================
__device__ __forceinline__ uint32_t smem_u32(const void* p) {
    uint32_t a;
    asm("{ .reg .u64 t; cvta.to.shared.u64 t, %1; cvt.u32.u64 %0, t; }" : "=r"(a) : "l"(p));
    return a;
}
__device__ __forceinline__ void cp_async16(uint32_t dst, const void* src) {
    asm volatile("cp.async.cg.shared.global [%0], [%1], 16;" :: "r"(dst), "l"(src));
}
#define CP_COMMIT() asm volatile("cp.async.commit_group;" ::: "memory")
#define CP_WAIT(n)  asm volatile("cp.async.wait_group %0;" :: "n"(n) : "memory")

__device__ __forceinline__ void ldsm_x4(uint32_t& r0, uint32_t& r1, uint32_t& r2, uint32_t& r3,
                                        uint32_t addr) {
    asm volatile("ldmatrix.sync.aligned.m8n8.x4.shared.b16 {%0,%1,%2,%3}, [%4];"
                 : "=r"(r0), "=r"(r1), "=r"(r2), "=r"(r3) : "r"(addr));
}
__device__ __forceinline__ void ldsm_x4_t(uint32_t& r0, uint32_t& r1, uint32_t& r2, uint32_t& r3,
                                          uint32_t addr) {
    asm volatile("ldmatrix.sync.aligned.m8n8.x4.trans.shared.b16 {%0,%1,%2,%3}, [%4];"
                 : "=r"(r0), "=r"(r1), "=r"(r2), "=r"(r3) : "r"(addr));
}
__device__ __forceinline__ void mma16816(float* c, uint32_t a0, uint32_t a1, uint32_t a2,
                                         uint32_t a3, uint32_t b0, uint32_t b1) {
    asm volatile(
        "mma.sync.aligned.m16n8k16.row.col.f32.f16.f16.f32 "
        "{%0,%1,%2,%3}, {%4,%5,%6,%7}, {%8,%9}, {%0,%1,%2,%3};"
        : "+f"(c[0]), "+f"(c[1]), "+f"(c[2]), "+f"(c[3])
        : "r"(a0), "r"(a1), "r"(a2), "r"(a3), "r"(b0), "r"(b1));
}
__device__ __forceinline__ void split2h(float a, float b, uint32_t& hi, uint32_t& lo) {
    __half ha = __float2half_rn(a), hb = __float2half_rn(b);
    float fa = __half2float(ha), fb = __half2float(hb);
    __half la = __float2half_rn(a - fa), lb = __float2half_rn(b - fb);
    hi = (uint32_t)__half_raw(ha).x | ((uint32_t)__half_raw(hb).x << 16);
    lo = (uint32_t)__half_raw(la).x | ((uint32_t)__half_raw(lb).x << 16);
}
__device__ __forceinline__ uint32_t round2h(float a, float b) {
    __half ha = __float2half_rn(a), hb = __float2half_rn(b);
    return (uint32_t)__half_raw(ha).x | ((uint32_t)__half_raw(hb).x << 16);
}

// ======================= split-fp16 conversion (inputs) =======================
__global__ void __launch_bounds__(256) split_f16_kernel(
    const float* __restrict__ in, uint16_t* __restrict__ out, int modeA, int total)
{
    int idx = blockIdx.x * 256 + threadIdx.x;
    if (idx >= total) return;
    const int r = idx >> 10;
    const int c = idx & 1023;
    const float v = in[idx];
    const __half hb = __float2half_rn(v);
    const float hf = __half2float(hb);
    const __half lb = __float2half_rn(v - hf);
    const uint16_t hu = __half_raw(hb).x;
    const uint16_t lu = __half_raw(lb).x;
    const size_t base = (size_t)r * KP2_ + c;
    out[base] = hu;
    out[base + 1024] = modeA ? lu : hu;
}

// ======================= fp16 GEMM: BK=64, 3-stage pipeline (unchanged R9) ========
#define BK_   64
#define NKT_  (KP2_ / BK_)   // 32
#define LDA_  72             // halves per smem row (144 B)
#define GS_TILE 18432        // 128 * 72 * 2
#define GS_STG  (2 * GS_TILE)   // A + B per stage = 36864
#define GS_SMEM (3 * GS_STG)    // 110592

__global__ void __launch_bounds__(256, 2) gemm_mma_kernel(
    const uint16_t* __restrict__ A, const uint16_t* __restrict__ Bm,
    float* __restrict__ C, int N)
{
    extern __shared__ char smem[];
    const uint32_t sbase = smem_u32(smem);

    const int tid  = threadIdx.x;
    const int wid  = tid >> 5;
    const int lane = tid & 31;
    const int wm = wid & 1;
    const int wn = wid >> 1;
    const int bm = blockIdx.y * 128;
    const int bn = blockIdx.x * 128;

    const int lrow = tid >> 1;
    const int lhalf = tid & 1;
    const uint16_t* Ag = A + (size_t)(bm + lrow) * KP2_ + lhalf * 32;
    const uint16_t* Bg = Bm + (size_t)(bn + lrow) * KP2_ + lhalf * 32;
    const uint32_t ldst = lrow * (LDA_ * 2) + lhalf * 64;

    const int a_row_l = ((lane >> 3) & 1) * 8 + (lane & 7);
    const int a_koff  = ((lane >> 4) & 1) * 8;
    const int b_row_l = ((lane >> 4) & 1) * 8 + (lane & 7);
    const int b_koff  = ((lane >> 3) & 1) * 8;

    float acc[4][4][4];
#pragma unroll
    for (int mi = 0; mi < 4; mi++)
#pragma unroll
        for (int ni = 0; ni < 4; ni++)
#pragma unroll
            for (int e = 0; e < 4; e++) acc[mi][ni][e] = 0.f;

    auto load_tile = [&](int kt, int stg) {
        const uint32_t dA = sbase + stg * GS_STG;
        const uint32_t dB = dA + GS_TILE;
        const uint16_t* ag = Ag + (size_t)kt * BK_;
        const uint16_t* bg = Bg + (size_t)kt * BK_;
#pragma unroll
        for (int u = 0; u < 4; u++) {
            cp_async16(dA + ldst + u * 16, ag + u * 8);
            cp_async16(dB + ldst + u * 16, bg + u * 8);
        }
    };

    load_tile(0, 0); CP_COMMIT();
    load_tile(1, 1); CP_COMMIT();

    int stg = 0;
    for (int kt = 0; kt < NKT_; kt++) {
        if (kt == NKT_ - 1) { CP_WAIT(0); } else { CP_WAIT(1); }
        __syncthreads();
        if (kt + 2 < NKT_) {
            int ns = stg + 2; if (ns >= 3) ns -= 3;
            load_tile(kt + 2, ns);
            CP_COMMIT();
        }
        const uint32_t sA = sbase + stg * GS_STG;
        const uint32_t sB = sA + GS_TILE;

#pragma unroll
        for (int ks = 0; ks < 4; ks++) {
            uint32_t a[4][4];
#pragma unroll
            for (int mi = 0; mi < 4; mi++) {
                const int row = wm * 64 + mi * 16 + a_row_l;
                ldsm_x4(a[mi][0], a[mi][1], a[mi][2], a[mi][3],
                        sA + (row * LDA_ + ks * 16 + a_koff) * 2);
            }
            uint32_t b[4][2];
#pragma unroll
            for (int np = 0; np < 2; np++) {
                const int row = wn * 32 + np * 16 + b_row_l;
                ldsm_x4(b[np * 2][0], b[np * 2][1], b[np * 2 + 1][0], b[np * 2 + 1][1],
                        sB + (row * LDA_ + ks * 16 + b_koff) * 2);
            }
#pragma unroll
            for (int mi = 0; mi < 4; mi++)
#pragma unroll
                for (int ni = 0; ni < 4; ni++)
                    mma16816(acc[mi][ni], a[mi][0], a[mi][1], a[mi][2], a[mi][3],
                             b[ni][0], b[ni][1]);
        }
        stg++; if (stg == 3) stg = 0;
    }

    const int er = lane >> 2;
    const int ec = (lane & 3) * 2;
#pragma unroll
    for (int mi = 0; mi < 4; mi++) {
#pragma unroll
        for (int ni = 0; ni < 4; ni++) {
            const int r0 = bm + wm * 64 + mi * 16 + er;
            const int c0 = bn + wn * 32 + ni * 8 + ec;
            *(float2*)(C + (size_t)r0 * N + c0)       = make_float2(acc[mi][ni][0], acc[mi][ni][1]);
            *(float2*)(C + (size_t)(r0 + 8) * N + c0) = make_float2(acc[mi][ni][2], acc[mi][ni][3]);
        }
    }
}

// ======================= RoPE trig table (fp64, tiny) =======================
__global__ void __launch_bounds__(256) rope_table_kernel(float2* __restrict__ tab)
{
    const int idx = blockIdx.x * 256 + threadIdx.x;   // t*32 + lane
    if (idx >= T_ * 32) return;
    const int t = idx >> 5, lane = idx & 31;
    const double freq = exp(-(double)lane * (9.210340371976184 / 32.0));
    double sd, cd;
    sincos((double)t * freq, &sd, &cd);
    tab[idx] = make_float2((float)cd, (float)sd);
}

// ======================= RoPE + head split -> fp16 Qh/Ql + Kh + Vh ==============
__global__ void __launch_bounds__(256) rope_split_kernel(
    const float* __restrict__ qkv, const float2* __restrict__ tab,
    uint16_t* __restrict__ qh, uint16_t* __restrict__ ql,
    uint16_t* __restrict__ kh, uint16_t* __restrict__ vh)
{
    const int w    = (blockIdx.x * blockDim.x + threadIdx.x) >> 5;
    const int lane = threadIdx.x & 31;
    const int t  = w & (T_ - 1);
    const int bh = w >> 11;
    const int b  = bh >> 4;
    const int h  = bh & 15;

    const size_t row = (size_t)(b * T_ + t) * TC_;
    const int col = h * HS_ + lane * 2;

    const float2 q2 = *(const float2*)(qkv + row + col);
    const float2 k2 = *(const float2*)(qkv + row + C_ + col);
    const float2 v2 = *(const float2*)(qkv + row + 2 * C_ + col);

    const float2 cs = tab[t * 32 + lane];
    const float c = cs.x, s = cs.y;

    const unsigned FULL = 0xffffffffu;
    float qp_prev = __shfl_sync(FULL, q2.y, (lane + 31) & 31);
    float qnr = q2.x * c - qp_prev * s;
    float qnr_next = __shfl_sync(FULL, qnr, (lane + 1) & 31);
    float qnp = q2.y * c + qnr_next * s;
    float kp_prev = __shfl_sync(FULL, k2.y, (lane + 31) & 31);
    float knr = k2.x * c - kp_prev * s;
    float knr_next = __shfl_sync(FULL, knr, (lane + 1) & 31);
    float knp = k2.y * c + knr_next * s;

    const size_t o = ((size_t)bh * T_ + t) * HS_ + lane * 2;
    uint32_t hi, lo;
    split2h(qnr, qnp, hi, lo);
    *(uint32_t*)(qh + o) = hi; *(uint32_t*)(ql + o) = lo;
    *(uint32_t*)(kh + o) = round2h(knr, knp);
    *(uint32_t*)(vh + o) = round2h(v2.x, v2.y);
}

// ======================= tensor-core causal flash attention (fp16) ==============
// 128 q per block (heavy-first order), 64 kv per tile, 3-stage, P single-term.
#define AT_ROWB 144
#define AT_TILE (64 * AT_ROWB)      // 9216 B
#define AT_BUF  (2 * AT_TILE)       // K + V per stage = 18432
#define AT_SMEM (3 * AT_BUF)        // 55296

__global__ void __launch_bounds__(256, 2) attn_mma_kernel(
    const uint16_t* __restrict__ Qh, const uint16_t* __restrict__ Ql,
    const uint16_t* __restrict__ Kh, const uint16_t* __restrict__ Vh,
    uint16_t* __restrict__ Ys)
{
    extern __shared__ char smem[];
    const uint32_t sbase = smem_u32(smem);
    const int tid = threadIdx.x, wid = tid >> 5, lane = tid & 31;
    const int bh = blockIdx.y;
    const int qt = (int)gridDim.x - 1 - (int)blockIdx.x;   // heavy blocks first
    const int q0 = qt * 128;
    const size_t hb = (size_t)bh * (T_ * HS_);

    const int a_row  = ((lane >> 3) & 1) * 8 + (lane & 7);
    const int a_koff = ((lane >> 4) & 1) * 8;
    const int b_row  = ((lane >> 4) & 1) * 8 + (lane & 7);
    const int b_koff = ((lane >> 3) & 1) * 8;
    const int v_row  = lane & 15;
    const int v_coff = (lane >> 4) << 3;

    // ---- stage Qh (stage0 area) + Ql (stage1 area) in ONE round ----
    uint32_t qhf[4][4], qlf[4][4];
    {
        const uint16_t* srch = Qh + hb + (size_t)q0 * HS_;
        const uint16_t* srcl = Ql + hb + (size_t)q0 * HS_;
        for (int i = tid; i < 1024; i += 256) {
            int row = i >> 3, cc = i & 7;
            cp_async16(sbase + row * AT_ROWB + cc * 16, srch + row * HS_ + cc * 8);
            cp_async16(sbase + AT_BUF + row * AT_ROWB + cc * 16, srcl + row * HS_ + cc * 8);
        }
        CP_COMMIT(); CP_WAIT(0); __syncthreads();
#pragma unroll
        for (int ks = 0; ks < 4; ks++) {
            ldsm_x4(qhf[ks][0], qhf[ks][1], qhf[ks][2], qhf[ks][3],
                    sbase + (wid * 16 + a_row) * AT_ROWB + (ks * 16 + a_koff) * 2);
            ldsm_x4(qlf[ks][0], qlf[ks][1], qlf[ks][2], qlf[ks][3],
                    sbase + AT_BUF + (wid * 16 + a_row) * AT_ROWB + (ks * 16 + a_koff) * 2);
        }
        __syncthreads();
    }

    float oc[8][4];
#pragma unroll
    for (int n = 0; n < 8; n++)
#pragma unroll
        for (int e = 0; e < 4; e++) oc[n][e] = 0.f;
    float m0 = -1e30f, m1 = -1e30f, l0 = 0.f, l1 = 0.f;
    const int wrow = q0 + wid * 16;
    const int nt = 2 * qt + 2;

    auto load_kv = [&](int kt, int stg) {
        const int k0 = kt * 64;
        const uint32_t dK = sbase + stg * AT_BUF;
        const uint32_t dV = dK + AT_TILE;
        const uint16_t* sk = Kh + hb + (size_t)k0 * HS_;
        const uint16_t* sv = Vh + hb + (size_t)k0 * HS_;
        for (int i = tid; i < 512; i += 256) {
            int row = i >> 3, cc = i & 7;
            cp_async16(dK + row * AT_ROWB + cc * 16, sk + row * HS_ + cc * 8);
            cp_async16(dV + row * AT_ROWB + cc * 16, sv + row * HS_ + cc * 8);
        }
    };

    load_kv(0, 0); CP_COMMIT();
    load_kv(1, 1); CP_COMMIT();

    int stg = 0;
    for (int kt = 0; kt < nt; kt++) {
        const int k0 = kt * 64;
        if (kt == nt - 1) { CP_WAIT(0); } else { CP_WAIT(1); }
        __syncthreads();
        if (kt + 2 < nt) {
            int ns = stg + 2; if (ns >= 3) ns -= 3;
            load_kv(kt + 2, ns);
            CP_COMMIT();
        }

        if (k0 <= wrow + 15) {
            const uint32_t kb = sbase + stg * AT_BUF;
            float sc[8][4];
#pragma unroll
            for (int n = 0; n < 8; n++)
#pragma unroll
                for (int e = 0; e < 4; e++) sc[n][e] = 0.f;

            // ---- S = Qh*Kh + Ql*Kh ----
#pragma unroll
            for (int ks = 0; ks < 4; ks++) {
                uint32_t kf[8][2];
#pragma unroll
                for (int np = 0; np < 4; np++)
                    ldsm_x4(kf[np * 2][0], kf[np * 2][1], kf[np * 2 + 1][0], kf[np * 2 + 1][1],
                            kb + (np * 16 + b_row) * AT_ROWB + (ks * 16 + b_koff) * 2);
#pragma unroll
                for (int n = 0; n < 8; n++) {
                    mma16816(sc[n], qhf[ks][0], qhf[ks][1], qhf[ks][2], qhf[ks][3], kf[n][0], kf[n][1]);
                    mma16816(sc[n], qlf[ks][0], qlf[ks][1], qlf[ks][2], qlf[ks][3], kf[n][0], kf[n][1]);
                }
            }

            // ---- scale + causal mask + row max ----
            const int r0g = wrow + (lane >> 2);
            const int r1g = r0g + 8;
            const int cb = k0 + (lane & 3) * 2;
            float mx0 = -1e30f, mx1 = -1e30f;
#pragma unroll
            for (int n = 0; n < 8; n++) {
                const int c0g = cb + n * 8, c1g = c0g + 1;
                sc[n][0] = (c0g > r0g) ? -1e30f : sc[n][0] * 0.125f;
                sc[n][1] = (c1g > r0g) ? -1e30f : sc[n][1] * 0.125f;
                sc[n][2] = (c0g > r1g) ? -1e30f : sc[n][2] * 0.125f;
                sc[n][3] = (c1g > r1g) ? -1e30f : sc[n][3] * 0.125f;
                mx0 = fmaxf(mx0, fmaxf(sc[n][0], sc[n][1]));
                mx1 = fmaxf(mx1, fmaxf(sc[n][2], sc[n][3]));
            }
            mx0 = fmaxf(mx0, __shfl_xor_sync(0xffffffffu, mx0, 1));
            mx0 = fmaxf(mx0, __shfl_xor_sync(0xffffffffu, mx0, 2));
            mx1 = fmaxf(mx1, __shfl_xor_sync(0xffffffffu, mx1, 1));
            mx1 = fmaxf(mx1, __shfl_xor_sync(0xffffffffu, mx1, 2));

            const float nm0 = fmaxf(m0, mx0), nm1 = fmaxf(m1, mx1);
            const float a0 = __expf(m0 - nm0), a1 = __expf(m1 - nm1);
            float s0 = 0.f, s1 = 0.f;
#pragma unroll
            for (int n = 0; n < 8; n++) {
                sc[n][0] = __expf(sc[n][0] - nm0); s0 += sc[n][0];
                sc[n][1] = __expf(sc[n][1] - nm0); s0 += sc[n][1];
                sc[n][2] = __expf(sc[n][2] - nm1); s1 += sc[n][2];
                sc[n][3] = __expf(sc[n][3] - nm1); s1 += sc[n][3];
            }
            s0 += __shfl_xor_sync(0xffffffffu, s0, 1);
            s0 += __shfl_xor_sync(0xffffffffu, s0, 2);
            s1 += __shfl_xor_sync(0xffffffffu, s1, 1);
            s1 += __shfl_xor_sync(0xffffffffu, s1, 2);
            l0 = l0 * a0 + s0; l1 = l1 * a1 + s1;
            m0 = nm0; m1 = nm1;

#pragma unroll
            for (int n = 0; n < 8; n++) {
                oc[n][0] *= a0; oc[n][1] *= a0; oc[n][2] *= a1; oc[n][3] *= a1;
            }

            // ---- pack P (single fp16 rounding; P in [0,1]) ----
            uint32_t ph[4][4];
#pragma unroll
            for (int j = 0; j < 4; j++) {
                ph[j][0] = round2h(sc[2 * j][0],     sc[2 * j][1]);
                ph[j][1] = round2h(sc[2 * j][2],     sc[2 * j][3]);
                ph[j][2] = round2h(sc[2 * j + 1][0], sc[2 * j + 1][1]);
                ph[j][3] = round2h(sc[2 * j + 1][2], sc[2 * j + 1][3]);
            }

            // ---- O += Ph*Vh ----
#pragma unroll
            for (int ks = 0; ks < 4; ks++) {
                uint32_t vf[8][2];
#pragma unroll
                for (int np = 0; np < 4; np++)
                    ldsm_x4_t(vf[np * 2][0], vf[np * 2][1], vf[np * 2 + 1][0], vf[np * 2 + 1][1],
                              kb + AT_TILE + (ks * 16 + v_row) * AT_ROWB + (np * 16 + v_coff) * 2);
#pragma unroll
                for (int n = 0; n < 8; n++)
                    mma16816(oc[n], ph[ks][0], ph[ks][1], ph[ks][2], ph[ks][3], vf[n][0], vf[n][1]);
            }
        }
        stg++; if (stg == 3) stg = 0;
    }

    // ---- epilogue: O/l, write split-y (hi,lo) directly ----
    const float il0 = 1.0f / l0, il1 = 1.0f / l1;
    const int b = bh >> 4, h = bh & 15;
    const int t0 = q0 + wid * 16 + (lane >> 2);
    uint16_t* y0 = Ys + ((size_t)b * T_ + t0) * KP2_;
    uint16_t* y1 = Ys + ((size_t)b * T_ + t0 + 8) * KP2_;
    const int col0 = h * 64 + (lane & 3) * 2;
#pragma unroll
    for (int n = 0; n < 8; n++) {
        const int cc = col0 + n * 8;
        uint32_t hi, lo;
        split2h(oc[n][0] * il0, oc[n][1] * il0, hi, lo);
        *(uint32_t*)(y0 + cc) = hi;
        *(uint32_t*)(y0 + cc + 1024) = lo;
        split2h(oc[n][2] * il1, oc[n][3] * il1, hi, lo);
        *(uint32_t*)(y1 + cc) = hi;
        *(uint32_t*)(y1 + cc + 1024) = lo;
    }
}

// ======================= launch =======================
extern "C" void kernel_launch(void* const* d_in, const int* in_sizes, int n_in,
                              void* d_out, int out_size)
{
    (void)in_sizes; (void)n_in; (void)out_size;
    const float* x      = (const float*)d_in[0];
    const float* w_attn = (const float*)d_in[1];
    const float* w_proj = (const float*)d_in[2];
    float* out = (float*)d_out;

    float* qkv;
    float2* tab;
    uint16_t *xs, *was, *wps, *ys, *qh, *ql, *kh, *vh;
    cudaGetSymbolAddress((void**)&qkv, g_qkv);
    cudaGetSymbolAddress((void**)&tab, g_rope);
    cudaGetSymbolAddress((void**)&xs,  g_xs);
    cudaGetSymbolAddress((void**)&was, g_was);
    cudaGetSymbolAddress((void**)&wps, g_wps);
    cudaGetSymbolAddress((void**)&ys,  g_ys);
    cudaGetSymbolAddress((void**)&qh,  g_qh);
    cudaGetSymbolAddress((void**)&ql,  g_ql);
    cudaGetSymbolAddress((void**)&kh,  g_kh);
    cudaGetSymbolAddress((void**)&vh,  g_vh);

    cudaFuncSetAttribute(gemm_mma_kernel, cudaFuncAttributeMaxDynamicSharedMemorySize, GS_SMEM);
    cudaFuncSetAttribute(attn_mma_kernel, cudaFuncAttributeMaxDynamicSharedMemorySize, AT_SMEM);

    // 0) rope table + split conversions of inputs
    rope_table_kernel<<<(T_ * 32 + 255) / 256, 256>>>(tab);
    {
        int n1 = MR_ * C_;
        split_f16_kernel<<<(n1 + 255) / 256, 256>>>(x, xs, 1, n1);
        int n2 = TC_ * C_;
        split_f16_kernel<<<(n2 + 255) / 256, 256>>>(w_attn, was, 0, n2);
        int n3 = C_ * C_;
        split_f16_kernel<<<(n3 + 255) / 256, 256>>>(w_proj, wps, 0, n3);
    }
    // 1) QKV = x' @ w_attn'^T
    {
        dim3 grid(TC_ / 128, MR_ / 128);
        gemm_mma_kernel<<<grid, 256, GS_SMEM>>>(xs, was, qkv, TC_);
    }
    // 2) RoPE + head split -> fp16 Qh/Ql, Kh, Vh
    {
        const int warps = B_ * H_ * T_;
        rope_split_kernel<<<warps * 32 / 256, 256>>>(qkv, tab, qh, ql, kh, vh);
    }
    // 3) tensor-core causal flash attention (emits split-y directly)
    {
        dim3 grid(T_ / 128, B_ * H_);
        attn_mma_kernel<<<grid, 256, AT_SMEM>>>(qh, ql, kh, vh, ys);
    }
    // 4) out = y' @ w_proj'^T
    {
        dim3 grid(C_ / 128, MR_ / 128);
        gemm_mma_kernel<<<grid, 256, GS_SMEM>>>(ys, wps, out, C_);
    }
}